// round 2
// baseline (speedup 1.0000x reference)
#include <cuda_runtime.h>
#include <math.h>
#include <stdint.h>

// ---------------------------------------------------------------------------
// Problem constants
// ---------------------------------------------------------------------------
constexpr int NB  = 8;
constexpr int LT  = 512;
constexpr int LS  = 512;
constexpr int D   = 512;
constexpr int H   = 8;
constexpr int DK  = 64;
constexpr int DV  = 64;
constexpr int DI  = 2048;
constexpr int NL  = 6;
constexpr int T   = NB * LT;

constexpr long long X_SIZE  = (long long)T * D;
constexpr long long ATT     = (long long)H * NB * LT * LT;
constexpr long long SLF_OFF = X_SIZE;
constexpr long long ENC_OFF = X_SIZE + (long long)NL * ATT;

// ---------------------------------------------------------------------------
// Scratch
// ---------------------------------------------------------------------------
__device__ float g_x  [T * D];
__device__ float g_q  [H * T * DK];
__device__ float g_k  [H * T * DK];
__device__ float g_v  [H * T * DK];
__device__ float g_ctx[T * D];
__device__ float g_h  [T * DI];

// ---------------------------------------------------------------------------
// tf32 helpers
// ---------------------------------------------------------------------------
__device__ __forceinline__ void split_tf32(float f, uint32_t& hi, uint32_t& lo) {
    asm("cvt.rna.tf32.f32 %0, %1;" : "=r"(hi) : "f"(f));
    float r = f - __uint_as_float(hi);
    asm("cvt.rna.tf32.f32 %0, %1;" : "=r"(lo) : "f"(r));
}

__device__ __forceinline__ void mma_tf32(float* d, const uint32_t* a,
                                         uint32_t b0, uint32_t b1) {
    asm volatile(
        "mma.sync.aligned.m16n8k8.row.col.f32.tf32.tf32.f32 "
        "{%0,%1,%2,%3}, {%4,%5,%6,%7}, {%8,%9}, {%0,%1,%2,%3};"
        : "+f"(d[0]), "+f"(d[1]), "+f"(d[2]), "+f"(d[3])
        : "r"(a[0]), "r"(a[1]), "r"(a[2]), "r"(a[3]), "r"(b0), "r"(b1));
}

// ---------------------------------------------------------------------------
// Tensor-core GEMM (3xTF32, near-fp32 precision)
//   C = alpha * A(MxK) * op(B)(KxN) (+bias)(+relu)
//   Block tile 128x64, BK=16, 128 threads (4 warps @ 64x32).
//   M%128==0, N%64==0, K%16==0 at all call sites.
// ---------------------------------------------------------------------------
__global__ __launch_bounds__(128) void gemm_tc(
    const float* __restrict__ A, int lda, long long sAo, long long sAi,
    const float* __restrict__ Bm, int ldb, long long sBo, long long sBi,
    float* __restrict__ C, int ldc, long long sCo, long long sCi,
    int K, int zdiv,
    float alpha, const float* __restrict__ bias, int relu, int transB)
{
    __shared__ uint32_t sA[2][128][20];   // [hi/lo][m][k]  (pad 20 -> conflict free)
    __shared__ uint32_t sB[2][64][20];    // [hi/lo][n][k]

    const int zo = blockIdx.z / zdiv;
    const int zi = blockIdx.z % zdiv;
    A  += (long long)zo * sAo + (long long)zi * sAi;
    Bm += (long long)zo * sBo + (long long)zi * sBi;
    C  += (long long)zo * sCo + (long long)zi * sCi;

    const int m0 = blockIdx.y * 128;
    const int n0 = blockIdx.x * 64;
    const int tid  = threadIdx.x;
    const int warp = tid >> 5, lane = tid & 31;
    const int g = lane >> 2, c = lane & 3;
    const int wm = (warp >> 1) * 64;   // warp row  (2 warps in M)
    const int wn = (warp & 1) * 32;    // warp col  (2 warps in N)

    float acc[4][4][4] = {};

    const int ar  = tid >> 2;      // 0..31
    const int aks = tid & 3;       // 0..3  (float4 slot)

    float4 pa[4];
    float4 pb[2];

    // ---- global prefetch of one k-chunk into registers
    auto ldg_chunk = [&](int k0) {
#pragma unroll
        for (int i = 0; i < 4; i++)
            pa[i] = *reinterpret_cast<const float4*>(
                A + (size_t)(m0 + i * 32 + ar) * lda + k0 + aks * 4);
        if (!transB) {
#pragma unroll
            for (int i = 0; i < 2; i++) {
                const int idx = i * 128 + tid;
                pb[i] = *reinterpret_cast<const float4*>(
                    Bm + (size_t)(k0 + (idx >> 4)) * ldb + n0 + (idx & 15) * 4);
            }
        } else {
#pragma unroll
            for (int i = 0; i < 2; i++) {
                const int idx = i * 128 + tid;
                pb[i] = *reinterpret_cast<const float4*>(
                    Bm + (size_t)(n0 + (idx >> 2)) * ldb + k0 + (idx & 3) * 4);
            }
        }
    };

    // ---- stage registers into smem with tf32 hi/lo split
    auto sts_chunk = [&]() {
#pragma unroll
        for (int i = 0; i < 4; i++) {
            const int row = i * 32 + ar;
            const float v[4] = {pa[i].x, pa[i].y, pa[i].z, pa[i].w};
#pragma unroll
            for (int j = 0; j < 4; j++) {
                uint32_t hi, lo;
                split_tf32(v[j], hi, lo);
                sA[0][row][aks * 4 + j] = hi;
                sA[1][row][aks * 4 + j] = lo;
            }
        }
        if (!transB) {
#pragma unroll
            for (int i = 0; i < 2; i++) {
                const int idx = i * 128 + tid;
                const int k = idx >> 4, nv = (idx & 15) * 4;
                const float v[4] = {pb[i].x, pb[i].y, pb[i].z, pb[i].w};
#pragma unroll
                for (int j = 0; j < 4; j++) {
                    uint32_t hi, lo;
                    split_tf32(v[j], hi, lo);
                    sB[0][nv + j][k] = hi;
                    sB[1][nv + j][k] = lo;
                }
            }
        } else {
#pragma unroll
            for (int i = 0; i < 2; i++) {
                const int idx = i * 128 + tid;
                const int nr = idx >> 2, ks = (idx & 3) * 4;
                const float v[4] = {pb[i].x, pb[i].y, pb[i].z, pb[i].w};
#pragma unroll
                for (int j = 0; j < 4; j++) {
                    uint32_t hi, lo;
                    split_tf32(v[j], hi, lo);
                    sB[0][nr][ks + j] = hi;
                    sB[1][nr][ks + j] = lo;
                }
            }
        }
    };

    ldg_chunk(0);
    for (int k0 = 0; k0 < K; k0 += 16) {
        __syncthreads();          // previous compute finished with smem
        sts_chunk();
        __syncthreads();
        if (k0 + 16 < K) ldg_chunk(k0 + 16);   // prefetch next while computing

#pragma unroll
        for (int kk = 0; kk < 16; kk += 8) {
            uint32_t ah[4][4], al[4][4];
#pragma unroll
            for (int mt = 0; mt < 4; mt++) {
                const int rb = wm + mt * 16;
                ah[mt][0] = sA[0][rb + g    ][kk + c];
                ah[mt][1] = sA[0][rb + g + 8][kk + c];
                ah[mt][2] = sA[0][rb + g    ][kk + c + 4];
                ah[mt][3] = sA[0][rb + g + 8][kk + c + 4];
                al[mt][0] = sA[1][rb + g    ][kk + c];
                al[mt][1] = sA[1][rb + g + 8][kk + c];
                al[mt][2] = sA[1][rb + g    ][kk + c + 4];
                al[mt][3] = sA[1][rb + g + 8][kk + c + 4];
            }
#pragma unroll
            for (int nt = 0; nt < 4; nt++) {
                const int nb = wn + nt * 8 + g;
                const uint32_t bh0 = sB[0][nb][kk + c];
                const uint32_t bh1 = sB[0][nb][kk + c + 4];
                const uint32_t bl0 = sB[1][nb][kk + c];
                const uint32_t bl1 = sB[1][nb][kk + c + 4];
#pragma unroll
                for (int mt = 0; mt < 4; mt++) {
                    mma_tf32(acc[mt][nt], ah[mt], bh0, bh1);  // hi*hi
                    mma_tf32(acc[mt][nt], ah[mt], bl0, bl1);  // hi*lo
                    mma_tf32(acc[mt][nt], al[mt], bh0, bh1);  // lo*hi
                }
            }
        }
    }

    // ---- epilogue
#pragma unroll
    for (int mt = 0; mt < 4; mt++) {
#pragma unroll
        for (int nt = 0; nt < 4; nt++) {
            const int row0 = m0 + wm + mt * 16 + g;
            const int col  = n0 + wn + nt * 8 + 2 * c;
            float b0 = 0.f, b1 = 0.f;
            if (bias) { b0 = bias[col]; b1 = bias[col + 1]; }
            float2 v0, v1;
            v0.x = acc[mt][nt][0] * alpha + b0;
            v0.y = acc[mt][nt][1] * alpha + b1;
            v1.x = acc[mt][nt][2] * alpha + b0;
            v1.y = acc[mt][nt][3] * alpha + b1;
            if (relu) {
                v0.x = fmaxf(v0.x, 0.f); v0.y = fmaxf(v0.y, 0.f);
                v1.x = fmaxf(v1.x, 0.f); v1.y = fmaxf(v1.y, 0.f);
            }
            *reinterpret_cast<float2*>(C + (size_t)row0 * ldc + col) = v0;
            *reinterpret_cast<float2*>(C + (size_t)(row0 + 8) * ldc + col) = v1;
        }
    }
}

// ---------------------------------------------------------------------------
// In-place masked softmax, rows of 512.  grid=(LT, H*NB)
// ---------------------------------------------------------------------------
__global__ void softmax_kernel(float* __restrict__ attn,
                               const int* __restrict__ seq, int causal)
{
    const int q  = blockIdx.x;
    const int hb = blockIdx.y;
    const int b  = hb % NB;
    float* row = attn + ((size_t)hb * LT + q) * (size_t)LT;
    const int tid = threadIdx.x;
    const int s0 = tid, s1 = tid + 256;

    float v0 = row[s0];
    float v1 = row[s1];
    if ((causal && s0 > q) || seq[b * LS + s0] == 0) v0 = -INFINITY;
    if ((causal && s1 > q) || seq[b * LS + s1] == 0) v1 = -INFINITY;

    __shared__ float red[256];
    red[tid] = fmaxf(v0, v1);
    __syncthreads();
    for (int off = 128; off > 0; off >>= 1) {
        if (tid < off) red[tid] = fmaxf(red[tid], red[tid + off]);
        __syncthreads();
    }
    const float m = red[0];
    __syncthreads();

    const float e0 = expf(v0 - m);
    const float e1 = expf(v1 - m);
    red[tid] = e0 + e1;
    __syncthreads();
    for (int off = 128; off > 0; off >>= 1) {
        if (tid < off) red[tid] += red[tid + off];
        __syncthreads();
    }
    const float inv = 1.0f / red[0];
    row[s0] = e0 * inv;
    row[s1] = e1 * inv;
}

// ---------------------------------------------------------------------------
// xout = LayerNorm(y + res) * g + b
// ---------------------------------------------------------------------------
__global__ void add_ln_kernel(const float* __restrict__ y,
                              const float* __restrict__ res,
                              float* __restrict__ xout,
                              const float* __restrict__ g,
                              const float* __restrict__ b)
{
    const int t = blockIdx.x;
    const int tid = threadIdx.x;
    const float* yr = y   + (size_t)t * D;
    const float* rr = res + (size_t)t * D;

    const float v0 = yr[tid] + rr[tid];
    const float v1 = yr[tid + 256] + rr[tid + 256];

    __shared__ float red[256];
    red[tid] = v0 + v1;
    __syncthreads();
    for (int off = 128; off > 0; off >>= 1) {
        if (tid < off) red[tid] += red[tid + off];
        __syncthreads();
    }
    const float mu = red[0] * (1.0f / 512.0f);
    __syncthreads();

    const float d0 = v0 - mu;
    const float d1 = v1 - mu;
    red[tid] = d0 * d0 + d1 * d1;
    __syncthreads();
    for (int off = 128; off > 0; off >>= 1) {
        if (tid < off) red[tid] += red[tid + off];
        __syncthreads();
    }
    const float var = red[0] * (1.0f / 512.0f);
    const float sc = rsqrtf(var + 1e-5f);

    xout[(size_t)t * D + tid]       = d0 * sc * g[tid]       + b[tid];
    xout[(size_t)t * D + tid + 256] = d1 * sc * g[tid + 256] + b[tid + 256];
}

__global__ void embed_kernel(const int* __restrict__ seq,
                             const int* __restrict__ pos,
                             const float* __restrict__ wemb,
                             const float* __restrict__ pemb,
                             float* __restrict__ x)
{
    const int t = blockIdx.x;
    const int tid = threadIdx.x;
    const size_t wo = (size_t)seq[t] * D;
    const size_t po = (size_t)pos[t] * D;
    x[(size_t)t * D + tid]       = wemb[wo + tid]       + pemb[po + tid];
    x[(size_t)t * D + tid + 256] = wemb[wo + tid + 256] + pemb[po + tid + 256];
}

__global__ void copy_kernel(const float* __restrict__ s, float* __restrict__ d,
                            long long n)
{
    long long i = (long long)blockIdx.x * blockDim.x + threadIdx.x;
    const long long stride = (long long)gridDim.x * blockDim.x;
    for (; i < n; i += stride) d[i] = s[i];
}

// ---------------------------------------------------------------------------
// Host-side launch helper
// ---------------------------------------------------------------------------
static inline void gemm(const float* A, int lda, long long sAo, long long sAi,
                        const float* Bm, int ldb, long long sBo, long long sBi,
                        float* C, int ldc, long long sCo, long long sCi,
                        int M, int N, int K, int Z, int zdiv,
                        float alpha, const float* bias, int relu, int transB)
{
    dim3 grid(N / 64, M / 128, Z);
    gemm_tc<<<grid, 128>>>(A, lda, sAo, sAi, Bm, ldb, sBo, sBi,
                           C, ldc, sCo, sCi, K, zdiv,
                           alpha, bias, relu, transB);
}

extern "C" void kernel_launch(void* const* d_in, const int* in_sizes, int n_in,
                              void* d_out, int out_size)
{
    const int*   tgt_seq    = (const int*)  d_in[0];
    const int*   tgt_pos    = (const int*)  d_in[1];
    const int*   src_seq    = (const int*)  d_in[2];
    const float* enc_output = (const float*)d_in[3];
    const float* tgt_emb    = (const float*)d_in[4];
    const float* pos_emb    = (const float*)d_in[5];
    const float* slf_wq     = (const float*)d_in[6];
    const float* slf_wk     = (const float*)d_in[7];
    const float* slf_wv     = (const float*)d_in[8];
    const float* slf_pw     = (const float*)d_in[9];
    const float* slf_pb     = (const float*)d_in[10];
    const float* slf_g      = (const float*)d_in[11];
    const float* slf_b      = (const float*)d_in[12];
    const float* enc_wq     = (const float*)d_in[13];
    const float* enc_wk     = (const float*)d_in[14];
    const float* enc_wv     = (const float*)d_in[15];
    const float* enc_pw     = (const float*)d_in[16];
    const float* enc_pb     = (const float*)d_in[17];
    const float* enc_g      = (const float*)d_in[18];
    const float* enc_b      = (const float*)d_in[19];
    const float* ffn_w1     = (const float*)d_in[20];
    const float* ffn_b1     = (const float*)d_in[21];
    const float* ffn_w2     = (const float*)d_in[22];
    const float* ffn_b2     = (const float*)d_in[23];
    const float* ffn_g      = (const float*)d_in[24];
    const float* ffn_b      = (const float*)d_in[25];

    float* out = (float*)d_out;

    float *x, *q, *k, *v, *ctx, *hbuf;
    cudaGetSymbolAddress((void**)&x,    g_x);
    cudaGetSymbolAddress((void**)&q,    g_q);
    cudaGetSymbolAddress((void**)&k,    g_k);
    cudaGetSymbolAddress((void**)&v,    g_v);
    cudaGetSymbolAddress((void**)&ctx,  g_ctx);
    cudaGetSymbolAddress((void**)&hbuf, g_h);

    const float scale = 1.0f / sqrtf((float)D);

    const long long HW   = (long long)H * D * DK;
    const long long sHT  = (long long)T * DK;
    const long long sBT  = (long long)LT * DK;
    const long long sAh  = (long long)NB * LT * LT;
    const long long sAb  = (long long)LT * LT;

    embed_kernel<<<T, 256>>>(tgt_seq, tgt_pos, tgt_emb, pos_emb, x);

    for (int l = 0; l < NL; l++) {
        // ================= self-attention =================
        gemm(x, D, 0, 0, slf_wq + (long long)l * HW, DK, (long long)D * DK, 0,
             q, DK, sHT, 0, T, DK, D, H, 1, 1.f, nullptr, 0, 0);
        gemm(x, D, 0, 0, slf_wk + (long long)l * HW, DK, (long long)D * DK, 0,
             k, DK, sHT, 0, T, DK, D, H, 1, 1.f, nullptr, 0, 0);
        gemm(x, D, 0, 0, slf_wv + (long long)l * HW, DK, (long long)D * DK, 0,
             v, DK, sHT, 0, T, DK, D, H, 1, 1.f, nullptr, 0, 0);

        float* attn = out + SLF_OFF + (long long)l * ATT;
        gemm(q, DK, sHT, sBT, k, DK, sHT, sBT,
             attn, LT, sAh, sAb, LT, LT, DK, H * NB, NB,
             scale, nullptr, 0, /*transB=*/1);
        softmax_kernel<<<dim3(LT, H * NB), 256>>>(attn, tgt_seq, 1);
        gemm(attn, LT, sAh, sAb, v, DK, sHT, sBT,
             ctx, H * DV, DV, (long long)LT * H * DV, LT, DK, LT, H * NB, NB,
             1.f, nullptr, 0, 0);
        gemm(ctx, D, 0, 0, slf_pw + (long long)l * D * D, D, 0, 0,
             hbuf, D, 0, 0, T, D, D, 1, 1, 1.f, slf_pb + (long long)l * D, 0, 0);
        add_ln_kernel<<<T, 256>>>(hbuf, x, x, slf_g + (long long)l * D,
                                  slf_b + (long long)l * D);

        // ================= cross-attention =================
        gemm(x, D, 0, 0, enc_wq + (long long)l * HW, DK, (long long)D * DK, 0,
             q, DK, sHT, 0, T, DK, D, H, 1, 1.f, nullptr, 0, 0);
        gemm(enc_output, D, 0, 0, enc_wk + (long long)l * HW, DK, (long long)D * DK, 0,
             k, DK, sHT, 0, T, DK, D, H, 1, 1.f, nullptr, 0, 0);
        gemm(enc_output, D, 0, 0, enc_wv + (long long)l * HW, DK, (long long)D * DK, 0,
             v, DK, sHT, 0, T, DK, D, H, 1, 1.f, nullptr, 0, 0);

        float* eattn = out + ENC_OFF + (long long)l * ATT;
        gemm(q, DK, sHT, sBT, k, DK, sHT, sBT,
             eattn, LS, sAh, sAb, LT, LS, DK, H * NB, NB,
             scale, nullptr, 0, /*transB=*/1);
        softmax_kernel<<<dim3(LT, H * NB), 256>>>(eattn, src_seq, 0);
        gemm(eattn, LS, sAh, sAb, v, DK, sHT, sBT,
             ctx, H * DV, DV, (long long)LT * H * DV, LT, DK, LS, H * NB, NB,
             1.f, nullptr, 0, 0);
        gemm(ctx, D, 0, 0, enc_pw + (long long)l * D * D, D, 0, 0,
             hbuf, D, 0, 0, T, D, D, 1, 1, 1.f, enc_pb + (long long)l * D, 0, 0);
        add_ln_kernel<<<T, 256>>>(hbuf, x, x, enc_g + (long long)l * D,
                                  enc_b + (long long)l * D);

        // ================= feed-forward =================
        gemm(x, D, 0, 0, ffn_w1 + (long long)l * D * DI, DI, 0, 0,
             hbuf, DI, 0, 0, T, DI, D, 1, 1, 1.f,
             ffn_b1 + (long long)l * DI, /*relu=*/1, 0);
        gemm(hbuf, DI, 0, 0, ffn_w2 + (long long)l * DI * D, D, 0, 0,
             ctx, D, 0, 0, T, D, DI, 1, 1, 1.f,
             ffn_b2 + (long long)l * D, 0, 0);
        add_ln_kernel<<<T, 256>>>(ctx, x, x, ffn_g + (long long)l * D,
                                  ffn_b + (long long)l * D);
    }

    copy_kernel<<<2048, 256>>>(x, out, X_SIZE);
}

// round 3
// speedup vs baseline: 2.0857x; 2.0857x over previous
#include <cuda_runtime.h>
#include <cuda_bf16.h>
#include <math.h>
#include <stdint.h>

// ---------------------------------------------------------------------------
// Problem constants
// ---------------------------------------------------------------------------
constexpr int NB  = 8;
constexpr int LT  = 512;
constexpr int LS  = 512;
constexpr int D   = 512;
constexpr int H   = 8;
constexpr int DK  = 64;
constexpr int DV  = 64;
constexpr int DI  = 2048;
constexpr int NL  = 6;
constexpr int T   = NB * LT;

constexpr long long X_SIZE  = (long long)T * D;
constexpr long long ATT     = (long long)H * NB * LT * LT;
constexpr long long SLF_OFF = X_SIZE;
constexpr long long ENC_OFF = X_SIZE + (long long)NL * ATT;

// ---------------------------------------------------------------------------
// Scratch (__device__ globals; ushort used as raw bf16 storage)
// ---------------------------------------------------------------------------
__device__ float g_x[T * D];
__device__ float g_y[T * D];

__device__ unsigned short g_wsh[NL * 3 * D * D], g_wsl[NL * 3 * D * D];
__device__ unsigned short g_weh[NL * 3 * D * D], g_wel[NL * 3 * D * D];
__device__ unsigned short g_ph [NL * 2 * D * D], g_pl [NL * 2 * D * D];
__device__ unsigned short g_f1h[NL * DI * D],    g_f1l[NL * DI * D];
__device__ unsigned short g_f2h[NL * D * DI],    g_f2l[NL * D * DI];

__device__ unsigned short g_xh[T * D], g_xl[T * D];
__device__ unsigned short g_eh[T * D], g_el[T * D];
__device__ unsigned short g_qh[T * D], g_ql[T * D];
__device__ unsigned short g_kh[T * D], g_kl[T * D];
__device__ unsigned short g_vh[T * D], g_vl[T * D];   // [b][h][e][s]
__device__ unsigned short g_ch[T * D], g_cl[T * D];
__device__ unsigned short g_hh[T * DI], g_hl[T * DI];
__device__ unsigned short g_ah[H * NB * LT * LT], g_al[H * NB * LT * LT];

// ---------------------------------------------------------------------------
// Helpers
// ---------------------------------------------------------------------------
__device__ __forceinline__ void bsplit(float v, __nv_bfloat16& h, __nv_bfloat16& l) {
    h = __float2bfloat16(v);
    l = __float2bfloat16(v - __bfloat162float(h));
}

__device__ __forceinline__ void ldsm4(uint32_t* r, uint32_t addr) {
    asm volatile("ldmatrix.sync.aligned.m8n8.x4.shared.b16 {%0,%1,%2,%3}, [%4];"
        : "=r"(r[0]), "=r"(r[1]), "=r"(r[2]), "=r"(r[3]) : "r"(addr));
}

__device__ __forceinline__ void mma_bf16(float* d, const uint32_t* a,
                                         uint32_t b0, uint32_t b1) {
    asm volatile(
        "mma.sync.aligned.m16n8k16.row.col.f32.bf16.bf16.f32 "
        "{%0,%1,%2,%3},{%4,%5,%6,%7},{%8,%9},{%0,%1,%2,%3};"
        : "+f"(d[0]), "+f"(d[1]), "+f"(d[2]), "+f"(d[3])
        : "r"(a[0]), "r"(a[1]), "r"(a[2]), "r"(a[3]), "r"(b0), "r"(b1));
}

__device__ __forceinline__ void cpasync16(uint32_t saddr, const void* g) {
    asm volatile("cp.async.cg.shared.global [%0], [%1], 16;" :: "r"(saddr), "l"(g));
}
__device__ __forceinline__ void cp_commit() { asm volatile("cp.async.commit_group;"); }
template<int N> __device__ __forceinline__ void cp_wait() {
    asm volatile("cp.async.wait_group %0;" :: "n"(N));
}

// swizzled smem byte offset for (row r of 64B, 16B-unit u)
__device__ __forceinline__ uint32_t swz(int r, int u) {
    return (uint32_t)((r << 6) + ((u ^ ((r >> 1) & 3)) << 4));
}

// ---------------------------------------------------------------------------
// bf16 3-product GEMM:  C = alpha*(Ah+Al)(Bh+Bl) (+bias)(+relu)
//   A: [M][K] planes (row-major, lda elems)   B: [N][K] planes (ldb elems)
//   mode 0: fp32 C     mode 1: bf16 hi/lo C   mode 2: bf16 hi/lo V-transposed
// ---------------------------------------------------------------------------
template<int BM, int BN, int WM, int WN>
__global__ __launch_bounds__(256, 1) void gemm_bf3(
    const __nv_bfloat16* __restrict__ Ah, const __nv_bfloat16* __restrict__ Al,
    int lda, long long sAo, long long sAi,
    const __nv_bfloat16* __restrict__ Bh, const __nv_bfloat16* __restrict__ Bl,
    int ldb, long long sBo, long long sBi,
    float* __restrict__ Cf, __nv_bfloat16* __restrict__ Ch,
    __nv_bfloat16* __restrict__ Cl,
    int ldc, long long sCo, long long sCi,
    int K, int zdiv, float alpha, const float* __restrict__ bias,
    int mode, int relu)
{
    constexpr int MT = WM / 16;
    constexpr int NT = WN / 8;
    constexpr int NP = WN / 16;
    constexpr int WCOL = BN / WN;
    constexpr int ABYTES = BM * 64;
    constexpr int BBYTES = BN * 64;

    extern __shared__ uint8_t smem[];
    const uint32_t sbase = (uint32_t)__cvta_generic_to_shared(smem);

    const int zo = blockIdx.z / zdiv;
    const int zi = blockIdx.z % zdiv;
    Ah += zo * sAo + zi * sAi;  Al += zo * sAo + zi * sAi;
    Bh += zo * sBo + zi * sBi;  Bl += zo * sBo + zi * sBi;
    const long long cOff = zo * sCo + zi * sCi;

    const int m0 = blockIdx.y * BM;
    const int n0 = blockIdx.x * BN;
    const int tid  = threadIdx.x;
    const int warp = tid >> 5, lane = tid & 31;
    const int wm = (warp / WCOL) * WM;
    const int wn = (warp % WCOL) * WN;

    float acc[MT][NT][4];
#pragma unroll
    for (int i = 0; i < MT; i++)
#pragma unroll
        for (int j = 0; j < NT; j++)
#pragma unroll
            for (int e = 0; e < 4; e++) acc[i][j][e] = 0.f;

    auto sA = [&](int buf, int p) { return sbase + (uint32_t)((buf * 2 + p) * ABYTES); };
    auto sB = [&](int buf, int p) { return sbase + (uint32_t)(4 * ABYTES + (buf * 2 + p) * BBYTES); };

    auto load_chunk = [&](int k0, int buf) {
#pragma unroll
        for (int p = 0; p < 2; p++) {
            const __nv_bfloat16* src = p ? Al : Ah;
#pragma unroll
            for (int i = 0; i < BM / 64; i++) {
                const int idx = tid + i * 256;
                const int r = idx >> 2, u = idx & 3;
                cpasync16(sA(buf, p) + swz(r, u),
                          src + (size_t)(m0 + r) * lda + k0 + u * 8);
            }
        }
#pragma unroll
        for (int p = 0; p < 2; p++) {
            const __nv_bfloat16* src = p ? Bl : Bh;
#pragma unroll
            for (int i = 0; i < BN / 64; i++) {
                const int idx = tid + i * 256;
                const int r = idx >> 2, u = idx & 3;
                cpasync16(sB(buf, p) + swz(r, u),
                          src + (size_t)(n0 + r) * ldb + k0 + u * 8);
            }
        }
        cp_commit();
    };

    auto compute = [&](int buf) {
#pragma unroll
        for (int ub = 0; ub < 4; ub += 2) {
            uint32_t a[2][MT][4];
#pragma unroll
            for (int p = 0; p < 2; p++)
#pragma unroll
                for (int mt = 0; mt < MT; mt++)
                    ldsm4(a[p][mt], sA(buf, p) +
                          swz(wm + mt * 16 + (lane & 15), ub + (lane >> 4)));
            uint32_t b[2][NP][4];
#pragma unroll
            for (int p = 0; p < 2; p++)
#pragma unroll
                for (int pr = 0; pr < NP; pr++)
                    ldsm4(b[p][pr], sB(buf, p) +
                          swz(wn + pr * 16 + ((lane & 16) >> 1) + (lane & 7),
                              ub + ((lane >> 3) & 1)));
#pragma unroll
            for (int nt = 0; nt < NT; nt++) {
                const int pr = nt >> 1, o = (nt & 1) * 2;
                const uint32_t bh0 = b[0][pr][o], bh1 = b[0][pr][o + 1];
                const uint32_t bl0 = b[1][pr][o], bl1 = b[1][pr][o + 1];
#pragma unroll
                for (int mt = 0; mt < MT; mt++) {
                    mma_bf16(acc[mt][nt], a[0][mt], bh0, bh1);
                    mma_bf16(acc[mt][nt], a[0][mt], bl0, bl1);
                    mma_bf16(acc[mt][nt], a[1][mt], bh0, bh1);
                }
            }
        }
    };

    const int NC = K / 32;
    load_chunk(0, 0);
    for (int c = 0; c < NC; c++) {
        if (c + 1 < NC) load_chunk((c + 1) * 32, (c + 1) & 1);
        if (c + 1 < NC) cp_wait<1>(); else cp_wait<0>();
        __syncthreads();
        compute(c & 1);
        __syncthreads();
    }

    // ---- epilogue
    const int g = lane >> 2, c2 = (lane & 3) * 2;
#pragma unroll
    for (int mt = 0; mt < MT; mt++) {
#pragma unroll
        for (int nt = 0; nt < NT; nt++) {
            const int mA = m0 + wm + mt * 16 + g;
            const int nA = n0 + wn + nt * 8 + c2;
            float b0 = 0.f, b1 = 0.f;
            if (bias) { b0 = bias[nA]; b1 = bias[nA + 1]; }
            float v0 = acc[mt][nt][0] * alpha + b0;
            float v1 = acc[mt][nt][1] * alpha + b1;
            float v2 = acc[mt][nt][2] * alpha + b0;
            float v3 = acc[mt][nt][3] * alpha + b1;
            if (relu) {
                v0 = fmaxf(v0, 0.f); v1 = fmaxf(v1, 0.f);
                v2 = fmaxf(v2, 0.f); v3 = fmaxf(v3, 0.f);
            }
            if (mode == 0) {
                float2 p0 = {v0, v1}, p1 = {v2, v3};
                *reinterpret_cast<float2*>(Cf + cOff + (size_t)mA * ldc + nA) = p0;
                *reinterpret_cast<float2*>(Cf + cOff + (size_t)(mA + 8) * ldc + nA) = p1;
            } else if (mode == 1) {
                __nv_bfloat16 h0, l0, h1, l1, h2, l2, h3, l3;
                bsplit(v0, h0, l0); bsplit(v1, h1, l1);
                bsplit(v2, h2, l2); bsplit(v3, h3, l3);
                __nv_bfloat162 ph0; ph0.x = h0; ph0.y = h1;
                __nv_bfloat162 pl0; pl0.x = l0; pl0.y = l1;
                __nv_bfloat162 ph1; ph1.x = h2; ph1.y = h3;
                __nv_bfloat162 pl1; pl1.x = l2; pl1.y = l3;
                *reinterpret_cast<__nv_bfloat162*>(Ch + cOff + (size_t)mA * ldc + nA) = ph0;
                *reinterpret_cast<__nv_bfloat162*>(Cl + cOff + (size_t)mA * ldc + nA) = pl0;
                *reinterpret_cast<__nv_bfloat162*>(Ch + cOff + (size_t)(mA + 8) * ldc + nA) = ph1;
                *reinterpret_cast<__nv_bfloat162*>(Cl + cOff + (size_t)(mA + 8) * ldc + nA) = pl1;
            } else {
                // V-transposed: out[b][h][e][s], t=(b,s)=row, n=(h,e)=col
                auto st = [&](int t, int nn, float val) {
                    __nv_bfloat16 hh, ll; bsplit(val, hh, ll);
                    const size_t idx = (size_t)(t >> 9) * (H * 64 * 512)
                                     + (size_t)(nn >> 6) * (64 * 512)
                                     + (size_t)(nn & 63) * 512 + (t & 511);
                    Ch[idx] = hh; Cl[idx] = ll;
                };
                st(mA, nA, v0); st(mA, nA + 1, v1);
                st(mA + 8, nA, v2); st(mA + 8, nA + 1, v3);
            }
        }
    }
}

// ---------------------------------------------------------------------------
// Transposed split:  plane[c][r] = split(in[r][c]); batched over z
// ---------------------------------------------------------------------------
__global__ void transpose_split(const float* __restrict__ in, long long inBatch,
                                int R, int C,
                                __nv_bfloat16* __restrict__ oh,
                                __nv_bfloat16* __restrict__ ol,
                                int outLd, long long outBatch)
{
    __shared__ float tile[32][33];
    const int z = blockIdx.z;
    in += (long long)z * inBatch;
    const long long ob = (long long)z * outBatch;
    const int r0 = blockIdx.y * 32, c0 = blockIdx.x * 32;
    const int tx = threadIdx.x, ty = threadIdx.y;
#pragma unroll
    for (int i = 0; i < 4; i++)
        tile[ty + i * 8][tx] = in[(size_t)(r0 + ty + i * 8) * C + c0 + tx];
    __syncthreads();
#pragma unroll
    for (int i = 0; i < 4; i++) {
        const float v = tile[tx][ty + i * 8];
        __nv_bfloat16 h, l; bsplit(v, h, l);
        const long long o = ob + (long long)(c0 + ty + i * 8) * outLd + r0 + tx;
        oh[o] = h; ol[o] = l;
    }
}

// elementwise split (enc_output)
__global__ void split_kernel(const float* __restrict__ in,
                             __nv_bfloat16* __restrict__ oh,
                             __nv_bfloat16* __restrict__ ol, long long n)
{
    long long i = (long long)blockIdx.x * blockDim.x + threadIdx.x;
    const long long stride = (long long)gridDim.x * blockDim.x;
    for (; i < n; i += stride) {
        __nv_bfloat16 h, l; bsplit(in[i], h, l);
        oh[i] = h; ol[i] = l;
    }
}

// ---------------------------------------------------------------------------
// Masked softmax (in-place on d_out rows) + bf16 split planes
// ---------------------------------------------------------------------------
__global__ void softmax_kernel(float* __restrict__ attn,
                               __nv_bfloat16* __restrict__ ah,
                               __nv_bfloat16* __restrict__ al,
                               const int* __restrict__ seq, int causal)
{
    const int q  = blockIdx.x;
    const int hb = blockIdx.y;
    const int b  = hb % NB;
    const size_t ro = ((size_t)hb * LT + q) * (size_t)LT;
    float* row = attn + ro;
    const int tid = threadIdx.x;
    const int s0 = tid, s1 = tid + 256;

    float v0 = row[s0];
    float v1 = row[s1];
    if ((causal && s0 > q) || seq[b * LS + s0] == 0) v0 = -INFINITY;
    if ((causal && s1 > q) || seq[b * LS + s1] == 0) v1 = -INFINITY;

    __shared__ float red[256];
    red[tid] = fmaxf(v0, v1);
    __syncthreads();
    for (int off = 128; off > 0; off >>= 1) {
        if (tid < off) red[tid] = fmaxf(red[tid], red[tid + off]);
        __syncthreads();
    }
    const float m = red[0];
    __syncthreads();

    const float e0 = expf(v0 - m);
    const float e1 = expf(v1 - m);
    red[tid] = e0 + e1;
    __syncthreads();
    for (int off = 128; off > 0; off >>= 1) {
        if (tid < off) red[tid] += red[tid + off];
        __syncthreads();
    }
    const float inv = 1.0f / red[0];
    const float p0 = e0 * inv, p1 = e1 * inv;
    row[s0] = p0; row[s1] = p1;
    __nv_bfloat16 h, l;
    bsplit(p0, h, l); ah[ro + s0] = h; al[ro + s0] = l;
    bsplit(p1, h, l); ah[ro + s1] = h; al[ro + s1] = l;
}

// ---------------------------------------------------------------------------
// x = LayerNorm(y + x) * g + b ; also emit split planes
// ---------------------------------------------------------------------------
__global__ void add_ln_kernel(const float* __restrict__ y,
                              float* __restrict__ x,
                              __nv_bfloat16* __restrict__ xh,
                              __nv_bfloat16* __restrict__ xl,
                              const float* __restrict__ g,
                              const float* __restrict__ b)
{
    const int t = blockIdx.x;
    const int tid = threadIdx.x;
    const float* yr = y + (size_t)t * D;
    float* xr = x + (size_t)t * D;

    const float v0 = yr[tid] + xr[tid];
    const float v1 = yr[tid + 256] + xr[tid + 256];

    __shared__ float red[256];
    red[tid] = v0 + v1;
    __syncthreads();
    for (int off = 128; off > 0; off >>= 1) {
        if (tid < off) red[tid] += red[tid + off];
        __syncthreads();
    }
    const float mu = red[0] * (1.0f / 512.0f);
    __syncthreads();

    const float d0 = v0 - mu;
    const float d1 = v1 - mu;
    red[tid] = d0 * d0 + d1 * d1;
    __syncthreads();
    for (int off = 128; off > 0; off >>= 1) {
        if (tid < off) red[tid] += red[tid + off];
        __syncthreads();
    }
    const float var = red[0] * (1.0f / 512.0f);
    const float sc = rsqrtf(var + 1e-5f);

    const float o0 = d0 * sc * g[tid] + b[tid];
    const float o1 = d1 * sc * g[tid + 256] + b[tid + 256];
    xr[tid] = o0; xr[tid + 256] = o1;
    __nv_bfloat16 h, l;
    bsplit(o0, h, l); xh[(size_t)t * D + tid] = h; xl[(size_t)t * D + tid] = l;
    bsplit(o1, h, l); xh[(size_t)t * D + tid + 256] = h; xl[(size_t)t * D + tid + 256] = l;
}

__global__ void embed_kernel(const int* __restrict__ seq,
                             const int* __restrict__ pos,
                             const float* __restrict__ wemb,
                             const float* __restrict__ pemb,
                             float* __restrict__ x,
                             __nv_bfloat16* __restrict__ xh,
                             __nv_bfloat16* __restrict__ xl)
{
    const int t = blockIdx.x;
    const int tid = threadIdx.x;
    const size_t wo = (size_t)seq[t] * D;
    const size_t po = (size_t)pos[t] * D;
    const float v0 = wemb[wo + tid] + pemb[po + tid];
    const float v1 = wemb[wo + tid + 256] + pemb[po + tid + 256];
    x[(size_t)t * D + tid] = v0;
    x[(size_t)t * D + tid + 256] = v1;
    __nv_bfloat16 h, l;
    bsplit(v0, h, l); xh[(size_t)t * D + tid] = h; xl[(size_t)t * D + tid] = l;
    bsplit(v1, h, l); xh[(size_t)t * D + tid + 256] = h; xl[(size_t)t * D + tid + 256] = l;
}

__global__ void copy_kernel(const float* __restrict__ s, float* __restrict__ d,
                            long long n)
{
    long long i = (long long)blockIdx.x * blockDim.x + threadIdx.x;
    const long long stride = (long long)gridDim.x * blockDim.x;
    for (; i < n; i += stride) d[i] = s[i];
}

// ---------------------------------------------------------------------------
// Host side
// ---------------------------------------------------------------------------
typedef __nv_bfloat16 bf;

struct GArgs {
    const bf *Ah, *Al; int lda; long long sAo, sAi;
    const bf *Bh, *Bl; int ldb; long long sBo, sBi;
    float* Cf; bf *Ch, *Cl; int ldc; long long sCo, sCi;
    int M, N, K, Z, zdiv; float alpha; const float* bias; int mode, relu;
};

static void g128(const GArgs& a) {
    dim3 grid(a.N / 128, a.M / 128, a.Z);
    gemm_bf3<128, 128, 64, 32><<<grid, 256, 65536>>>(
        a.Ah, a.Al, a.lda, a.sAo, a.sAi, a.Bh, a.Bl, a.ldb, a.sBo, a.sBi,
        a.Cf, a.Ch, a.Cl, a.ldc, a.sCo, a.sCi, a.K, a.zdiv, a.alpha, a.bias,
        a.mode, a.relu);
}
static void g64(const GArgs& a) {
    dim3 grid(a.N / 64, a.M / 128, a.Z);
    gemm_bf3<128, 64, 32, 32><<<grid, 256, 49152>>>(
        a.Ah, a.Al, a.lda, a.sAo, a.sAi, a.Bh, a.Bl, a.ldb, a.sBo, a.sBi,
        a.Cf, a.Ch, a.Cl, a.ldc, a.sCo, a.sCi, a.K, a.zdiv, a.alpha, a.bias,
        a.mode, a.relu);
}

extern "C" void kernel_launch(void* const* d_in, const int* in_sizes, int n_in,
                              void* d_out, int out_size)
{
    const int*   tgt_seq    = (const int*)  d_in[0];
    const int*   tgt_pos    = (const int*)  d_in[1];
    const int*   src_seq    = (const int*)  d_in[2];
    const float* enc_output = (const float*)d_in[3];
    const float* tgt_emb    = (const float*)d_in[4];
    const float* pos_emb    = (const float*)d_in[5];
    const float* slf_wq     = (const float*)d_in[6];
    const float* slf_wk     = (const float*)d_in[7];
    const float* slf_wv     = (const float*)d_in[8];
    const float* slf_pw     = (const float*)d_in[9];
    const float* slf_pb     = (const float*)d_in[10];
    const float* slf_g      = (const float*)d_in[11];
    const float* slf_b      = (const float*)d_in[12];
    const float* enc_wq     = (const float*)d_in[13];
    const float* enc_wk     = (const float*)d_in[14];
    const float* enc_wv     = (const float*)d_in[15];
    const float* enc_pw     = (const float*)d_in[16];
    const float* enc_pb     = (const float*)d_in[17];
    const float* enc_g      = (const float*)d_in[18];
    const float* enc_b      = (const float*)d_in[19];
    const float* ffn_w1     = (const float*)d_in[20];
    const float* ffn_b1     = (const float*)d_in[21];
    const float* ffn_w2     = (const float*)d_in[22];
    const float* ffn_b2     = (const float*)d_in[23];
    const float* ffn_g      = (const float*)d_in[24];
    const float* ffn_b      = (const float*)d_in[25];

    float* out = (float*)d_out;

    static bool attrDone = false;
    if (!attrDone) {
        cudaFuncSetAttribute((const void*)gemm_bf3<128, 128, 64, 32>,
                             cudaFuncAttributeMaxDynamicSharedMemorySize, 65536);
        cudaFuncSetAttribute((const void*)gemm_bf3<128, 64, 32, 32>,
                             cudaFuncAttributeMaxDynamicSharedMemorySize, 49152);
        attrDone = true;
    }

    float *x, *y;
    cudaGetSymbolAddress((void**)&x, g_x);
    cudaGetSymbolAddress((void**)&y, g_y);
    auto sym = [](const void* s) {
        void* p; cudaGetSymbolAddress(&p, s); return (bf*)p;
    };
    bf *wsh = sym(g_wsh), *wsl = sym(g_wsl);
    bf *weh = sym(g_weh), *wel = sym(g_wel);
    bf *ph  = sym(g_ph),  *pl  = sym(g_pl);
    bf *f1h = sym(g_f1h), *f1l = sym(g_f1l);
    bf *f2h = sym(g_f2h), *f2l = sym(g_f2l);
    bf *xh = sym(g_xh), *xl = sym(g_xl);
    bf *eh = sym(g_eh), *el = sym(g_el);
    bf *qh = sym(g_qh), *ql = sym(g_ql);
    bf *kh = sym(g_kh), *kl = sym(g_kl);
    bf *vh = sym(g_vh), *vl = sym(g_vl);
    bf *ch = sym(g_ch), *cl = sym(g_cl);
    bf *hh = sym(g_hh), *hl = sym(g_hl);
    bf *ah = sym(g_ah), *al = sym(g_al);

    const float scale = 1.0f / sqrtf((float)D);
    const long long DD = (long long)D * D;

    // ---------- weight prep ----------
    split_kernel<<<2048, 256>>>(enc_output, eh, el, X_SIZE);
    const float* sW[3] = {slf_wq, slf_wk, slf_wv};
    const float* eW[3] = {enc_wq, enc_wk, enc_wv};
    for (int l = 0; l < NL; l++) {
        for (int w = 0; w < 3; w++) {
            transpose_split<<<dim3(2, 16, 8), dim3(32, 8)>>>(
                sW[w] + (long long)l * H * D * DK, (long long)D * DK, D, DK,
                wsh + ((long long)l * 3 + w) * DD, wsl + ((long long)l * 3 + w) * DD,
                D, (long long)DK * D);
            transpose_split<<<dim3(2, 16, 8), dim3(32, 8)>>>(
                eW[w] + (long long)l * H * D * DK, (long long)D * DK, D, DK,
                weh + ((long long)l * 3 + w) * DD, wel + ((long long)l * 3 + w) * DD,
                D, (long long)DK * D);
        }
        transpose_split<<<dim3(16, 16, 1), dim3(32, 8)>>>(
            slf_pw + (long long)l * DD, 0, D, D,
            ph + ((long long)l * 2 + 0) * DD, pl + ((long long)l * 2 + 0) * DD, D, 0);
        transpose_split<<<dim3(16, 16, 1), dim3(32, 8)>>>(
            enc_pw + (long long)l * DD, 0, D, D,
            ph + ((long long)l * 2 + 1) * DD, pl + ((long long)l * 2 + 1) * DD, D, 0);
        transpose_split<<<dim3(64, 16, 1), dim3(32, 8)>>>(
            ffn_w1 + (long long)l * D * DI, 0, D, DI,
            f1h + (long long)l * DI * D, f1l + (long long)l * DI * D, D, 0);
        transpose_split<<<dim3(16, 64, 1), dim3(32, 8)>>>(
            ffn_w2 + (long long)l * DI * D, 0, DI, D,
            f2h + (long long)l * D * DI, f2l + (long long)l * D * DI, DI, 0);
    }

    embed_kernel<<<T, 256>>>(tgt_seq, tgt_pos, tgt_emb, pos_emb, x, xh, xl);

    const long long sAh_ = (long long)NB * LT * LT;  // attn head stride
    const long long sAb_ = (long long)LT * LT;

    for (int l = 0; l < NL; l++) {
        for (int pass = 0; pass < 2; pass++) {
            const bool self = (pass == 0);
            const bf* Wh = (self ? wsh : weh) + (long long)l * 3 * DD;
            const bf* Wl = (self ? wsl : wel) + (long long)l * 3 * DD;
            const bf* inh = self ? xh : eh;
            const bf* inl = self ? xl : el;
            // Q (always from x)
            { GArgs a = {xh, xl, D, 0, 0, Wh, Wl, D, 0, 0,
                         nullptr, qh, ql, D, 0, 0, T, D, D, 1, 1, 1.f, nullptr, 1, 0};
              g128(a); }
            // K
            { GArgs a = {inh, inl, D, 0, 0, Wh + DD, Wl + DD, D, 0, 0,
                         nullptr, kh, kl, D, 0, 0, T, D, D, 1, 1, 1.f, nullptr, 1, 0};
              g128(a); }
            // V (transposed epilogue)
            { GArgs a = {inh, inl, D, 0, 0, Wh + 2 * DD, Wl + 2 * DD, D, 0, 0,
                         nullptr, vh, vl, 0, 0, 0, T, D, D, 1, 1, 1.f, nullptr, 2, 0};
              g128(a); }
            // scores -> d_out
            float* attn = out + (self ? SLF_OFF : ENC_OFF) + (long long)l * ATT;
            { GArgs a = {qh, ql, D, 64, sAb_, kh, kl, D, 64, sAb_,
                         attn, nullptr, nullptr, LT, sAh_, sAb_,
                         LT, LT, DK, H * NB, NB, scale, nullptr, 0, 0};
              g128(a); }
            softmax_kernel<<<dim3(LT, H * NB), 256>>>(
                attn, ah, al, self ? tgt_seq : src_seq, self ? 1 : 0);
            // AV -> ctx planes
            { GArgs a = {ah, al, LT, sAh_, sAb_, vh, vl, LT,
                         (long long)64 * 512, (long long)H * 64 * 512,
                         nullptr, ch, cl, D, 64, sAb_,
                         LT, DV, LT, H * NB, NB, 1.f, nullptr, 1, 0};
              g64(a); }
            // proj -> y (fp32)
            const bf* pwh = ph + ((long long)l * 2 + (self ? 0 : 1)) * DD;
            const bf* pwl = pl + ((long long)l * 2 + (self ? 0 : 1)) * DD;
            const float* pb = (self ? slf_pb : enc_pb) + (long long)l * D;
            { GArgs a = {ch, cl, D, 0, 0, pwh, pwl, D, 0, 0,
                         y, nullptr, nullptr, D, 0, 0, T, D, D, 1, 1, 1.f, pb, 0, 0};
              g128(a); }
            add_ln_kernel<<<T, 256>>>(y, x, xh, xl,
                (self ? slf_g : enc_g) + (long long)l * D,
                (self ? slf_b : enc_b) + (long long)l * D);
        }
        // FFN
        { GArgs a = {xh, xl, D, 0, 0, f1h + (long long)l * DI * D,
                     f1l + (long long)l * DI * D, D, 0, 0,
                     nullptr, hh, hl, DI, 0, 0, T, DI, D, 1, 1, 1.f,
                     ffn_b1 + (long long)l * DI, 1, 1};
          g128(a); }
        { GArgs a = {hh, hl, DI, 0, 0, f2h + (long long)l * D * DI,
                     f2l + (long long)l * D * DI, DI, 0, 0,
                     y, nullptr, nullptr, D, 0, 0, T, D, DI, 1, 1, 1.f,
                     ffn_b2 + (long long)l * D, 0, 0};
          g128(a); }
        add_ln_kernel<<<T, 256>>>(y, x, xh, xl,
            ffn_g + (long long)l * D, ffn_b + (long long)l * D);
    }

    copy_kernel<<<2048, 256>>>(x, out, X_SIZE);
}

// round 14
// speedup vs baseline: 2.2106x; 1.0599x over previous
#include <cuda_runtime.h>
#include <cuda_bf16.h>
#include <math.h>
#include <stdint.h>

// ---------------------------------------------------------------------------
// Problem constants
// ---------------------------------------------------------------------------
constexpr int NB  = 8;
constexpr int LT  = 512;
constexpr int LS  = 512;
constexpr int D   = 512;
constexpr int H   = 8;
constexpr int DK  = 64;
constexpr int DV  = 64;
constexpr int DI  = 2048;
constexpr int NL  = 6;
constexpr int T   = NB * LT;

constexpr long long X_SIZE  = (long long)T * D;
constexpr long long ATT     = (long long)H * NB * LT * LT;
constexpr long long SLF_OFF = X_SIZE;
constexpr long long ENC_OFF = X_SIZE + (long long)NL * ATT;

// ---------------------------------------------------------------------------
// Scratch
// ---------------------------------------------------------------------------
__device__ float g_x[T * D];
__device__ float g_y[T * D];

__device__ unsigned short g_wsh[NL * 3 * D * D], g_wsl[NL * 3 * D * D];
__device__ unsigned short g_weh[NL * 3 * D * D], g_wel[NL * 3 * D * D];
__device__ unsigned short g_ph [NL * 2 * D * D], g_pl [NL * 2 * D * D];
__device__ unsigned short g_f1h[NL * DI * D],    g_f1l[NL * DI * D];
__device__ unsigned short g_f2h[NL * D * DI],    g_f2l[NL * D * DI];

__device__ unsigned short g_xh[T * D], g_xl[T * D];
__device__ unsigned short g_eh[T * D], g_el[T * D];
__device__ unsigned short g_qh[T * D], g_ql[T * D];
__device__ unsigned short g_kh[T * D], g_kl[T * D];
__device__ unsigned short g_vh[T * D], g_vl[T * D];   // [b][h][e][s]
__device__ unsigned short g_ch[T * D], g_cl[T * D];
__device__ unsigned short g_hh[T * DI], g_hl[T * DI];
__device__ unsigned short g_ah[H * NB * LT * LT], g_al[H * NB * LT * LT];

// ---------------------------------------------------------------------------
// Helpers
// ---------------------------------------------------------------------------
typedef __nv_bfloat16 bf;

__device__ __forceinline__ void bsplit(float v, bf& h, bf& l) {
    h = __float2bfloat16(v);
    l = __float2bfloat16(v - __bfloat162float(h));
}

__device__ __forceinline__ void ldsm4(uint32_t* r, uint32_t addr) {
    asm volatile("ldmatrix.sync.aligned.m8n8.x4.shared.b16 {%0,%1,%2,%3}, [%4];"
        : "=r"(r[0]), "=r"(r[1]), "=r"(r[2]), "=r"(r[3]) : "r"(addr));
}

__device__ __forceinline__ void mma_bf16(float* d, const uint32_t* a,
                                         uint32_t b0, uint32_t b1) {
    asm volatile(
        "mma.sync.aligned.m16n8k16.row.col.f32.bf16.bf16.f32 "
        "{%0,%1,%2,%3},{%4,%5,%6,%7},{%8,%9},{%0,%1,%2,%3};"
        : "+f"(d[0]), "+f"(d[1]), "+f"(d[2]), "+f"(d[3])
        : "r"(a[0]), "r"(a[1]), "r"(a[2]), "r"(a[3]), "r"(b0), "r"(b1));
}

__device__ __forceinline__ void cpasync16(uint32_t saddr, const void* g) {
    asm volatile("cp.async.cg.shared.global [%0], [%1], 16;" :: "r"(saddr), "l"(g));
}
__device__ __forceinline__ void cp_commit() { asm volatile("cp.async.commit_group;"); }
template<int N> __device__ __forceinline__ void cp_wait() {
    asm volatile("cp.async.wait_group %0;" :: "n"(N));
}

// swizzled smem byte offset for (row r of 64B, 16B-unit u)
__device__ __forceinline__ uint32_t swz(int r, int u) {
    return (uint32_t)((r << 6) + ((u ^ ((r >> 1) & 3)) << 4));
}

// ---------------------------------------------------------------------------
// bf16 3-product GEMM (mma.sync):  C = alpha*(Ah+Al)(Bh+Bl) (+bias)(+relu)
//   A: [M][K] planes (row-major, lda)   B: [N][K] planes (ldb)
//   3-stage cp.async pipeline, one __syncthreads per 32-K chunk.
//   mode 0: fp32 C   mode 1: bf16 hi/lo C   mode 2: bf16 hi/lo V-transposed
// ---------------------------------------------------------------------------
template<int BM, int BN, int WM, int WN>
__global__ __launch_bounds__(256, 1) void gemm_bf3(
    const bf* __restrict__ Ah, const bf* __restrict__ Al,
    int lda, long long sAo, long long sAi,
    const bf* __restrict__ Bh, const bf* __restrict__ Bl,
    int ldb, long long sBo, long long sBi,
    float* __restrict__ Cf, bf* __restrict__ Ch, bf* __restrict__ Cl,
    int ldc, long long sCo, long long sCi,
    int K, int zdiv, float alpha, const float* __restrict__ bias,
    int mode, int relu)
{
    constexpr int MT = WM / 16;
    constexpr int NT = WN / 8;
    constexpr int NP = WN / 16;
    constexpr int WCOL = BN / WN;
    constexpr int ABYTES = BM * 64;   // one plane, one chunk (BM x 32 bf16)
    constexpr int BBYTES = BN * 64;

    extern __shared__ uint8_t smem[];
    const uint32_t sbase = (uint32_t)__cvta_generic_to_shared(smem);

    const int zo = blockIdx.z / zdiv;
    const int zi = blockIdx.z % zdiv;
    Ah += zo * sAo + zi * sAi;  Al += zo * sAo + zi * sAi;
    Bh += zo * sBo + zi * sBi;  Bl += zo * sBo + zi * sBi;
    const long long cOff = zo * sCo + zi * sCi;

    const int m0 = blockIdx.y * BM;
    const int n0 = blockIdx.x * BN;
    const int tid  = threadIdx.x;
    const int warp = tid >> 5, lane = tid & 31;
    const int wm = (warp / WCOL) * WM;
    const int wn = (warp % WCOL) * WN;

    float acc[MT][NT][4];
#pragma unroll
    for (int i = 0; i < MT; i++)
#pragma unroll
        for (int j = 0; j < NT; j++)
#pragma unroll
            for (int e = 0; e < 4; e++) acc[i][j][e] = 0.f;

    // 3 stages: A region = 6 planes, then B region = 6 planes
    auto sA = [&](int buf, int p) { return sbase + (uint32_t)((buf * 2 + p) * ABYTES); };
    auto sB = [&](int buf, int p) { return sbase + (uint32_t)(6 * ABYTES + (buf * 2 + p) * BBYTES); };

    auto load_chunk = [&](int k0, int buf) {
#pragma unroll
        for (int p = 0; p < 2; p++) {
            const bf* src = p ? Al : Ah;
#pragma unroll
            for (int i = 0; i < BM / 64; i++) {
                const int idx = tid + i * 256;
                const int r = idx >> 2, u = idx & 3;
                cpasync16(sA(buf, p) + swz(r, u),
                          src + (size_t)(m0 + r) * lda + k0 + u * 8);
            }
        }
#pragma unroll
        for (int p = 0; p < 2; p++) {
            const bf* src = p ? Bl : Bh;
#pragma unroll
            for (int i = 0; i < BN / 64; i++) {
                const int idx = tid + i * 256;
                const int r = idx >> 2, u = idx & 3;
                cpasync16(sB(buf, p) + swz(r, u),
                          src + (size_t)(n0 + r) * ldb + k0 + u * 8);
            }
        }
        cp_commit();
    };

    auto compute = [&](int buf) {
#pragma unroll
        for (int ub = 0; ub < 4; ub += 2) {
            uint32_t a[2][MT][4];
#pragma unroll
            for (int p = 0; p < 2; p++)
#pragma unroll
                for (int mt = 0; mt < MT; mt++)
                    ldsm4(a[p][mt], sA(buf, p) +
                          swz(wm + mt * 16 + (lane & 15), ub + (lane >> 4)));
            uint32_t b[2][NP][4];
#pragma unroll
            for (int p = 0; p < 2; p++)
#pragma unroll
                for (int pr = 0; pr < NP; pr++)
                    ldsm4(b[p][pr], sB(buf, p) +
                          swz(wn + pr * 16 + ((lane & 16) >> 1) + (lane & 7),
                              ub + ((lane >> 3) & 1)));
#pragma unroll
            for (int nt = 0; nt < NT; nt++) {
                const int pr = nt >> 1, o = (nt & 1) * 2;
                const uint32_t bh0 = b[0][pr][o], bh1 = b[0][pr][o + 1];
                const uint32_t bl0 = b[1][pr][o], bl1 = b[1][pr][o + 1];
#pragma unroll
                for (int mt = 0; mt < MT; mt++) {
                    mma_bf16(acc[mt][nt], a[0][mt], bh0, bh1);
                    mma_bf16(acc[mt][nt], a[0][mt], bl0, bl1);
                    mma_bf16(acc[mt][nt], a[1][mt], bh0, bh1);
                }
            }
        }
    };

    const int NC = K / 32;
    load_chunk(0, 0);
    if (NC > 1) load_chunk(32, 1);
    for (int c = 0; c < NC; c++) {
        if (c + 1 < NC) cp_wait<1>(); else cp_wait<0>();
        __syncthreads();
        if (c + 2 < NC) load_chunk((c + 2) * 32, (c + 2) % 3);
        compute(c % 3);
    }

    // ---- epilogue
    const int g = lane >> 2, c2 = (lane & 3) * 2;
#pragma unroll
    for (int mt = 0; mt < MT; mt++) {
#pragma unroll
        for (int nt = 0; nt < NT; nt++) {
            const int mA = m0 + wm + mt * 16 + g;
            const int nA = n0 + wn + nt * 8 + c2;
            float b0 = 0.f, b1 = 0.f;
            if (bias) { b0 = bias[nA]; b1 = bias[nA + 1]; }
            float v0 = acc[mt][nt][0] * alpha + b0;
            float v1 = acc[mt][nt][1] * alpha + b1;
            float v2 = acc[mt][nt][2] * alpha + b0;
            float v3 = acc[mt][nt][3] * alpha + b1;
            if (relu) {
                v0 = fmaxf(v0, 0.f); v1 = fmaxf(v1, 0.f);
                v2 = fmaxf(v2, 0.f); v3 = fmaxf(v3, 0.f);
            }
            if (mode == 0) {
                float2 p0 = {v0, v1}, p1 = {v2, v3};
                *reinterpret_cast<float2*>(Cf + cOff + (size_t)mA * ldc + nA) = p0;
                *reinterpret_cast<float2*>(Cf + cOff + (size_t)(mA + 8) * ldc + nA) = p1;
            } else if (mode == 1) {
                bf h0, l0, h1, l1, h2, l2, h3, l3;
                bsplit(v0, h0, l0); bsplit(v1, h1, l1);
                bsplit(v2, h2, l2); bsplit(v3, h3, l3);
                __nv_bfloat162 ph0; ph0.x = h0; ph0.y = h1;
                __nv_bfloat162 pl0; pl0.x = l0; pl0.y = l1;
                __nv_bfloat162 ph1; ph1.x = h2; ph1.y = h3;
                __nv_bfloat162 pl1; pl1.x = l2; pl1.y = l3;
                *reinterpret_cast<__nv_bfloat162*>(Ch + cOff + (size_t)mA * ldc + nA) = ph0;
                *reinterpret_cast<__nv_bfloat162*>(Cl + cOff + (size_t)mA * ldc + nA) = pl0;
                *reinterpret_cast<__nv_bfloat162*>(Ch + cOff + (size_t)(mA + 8) * ldc + nA) = ph1;
                *reinterpret_cast<__nv_bfloat162*>(Cl + cOff + (size_t)(mA + 8) * ldc + nA) = pl1;
            } else {
                // V-transposed: out[b][h][e][s], t=(b,s)=row, n=(h,e)=col
                auto st = [&](int t, int nn, float val) {
                    bf hh, ll; bsplit(val, hh, ll);
                    const size_t idx = (size_t)(t >> 9) * (H * 64 * 512)
                                     + (size_t)(nn >> 6) * (64 * 512)
                                     + (size_t)(nn & 63) * 512 + (t & 511);
                    Ch[idx] = hh; Cl[idx] = ll;
                };
                st(mA, nA, v0); st(mA, nA + 1, v1);
                st(mA + 8, nA, v2); st(mA + 8, nA + 1, v3);
            }
        }
    }
}

// ---------------------------------------------------------------------------
// Transposed split with (zo, zi) batching:
//   plane[c][r] = split(in[r][c]);  in += z*inBatch;  out += zo*outBO + zi*outBI
// ---------------------------------------------------------------------------
__global__ void transpose_split(const float* __restrict__ in, long long inBatch,
                                int C, bf* __restrict__ oh, bf* __restrict__ ol,
                                int outLd, long long outBO, long long outBI,
                                int zdiv)
{
    __shared__ float tile[32][33];
    const int z = blockIdx.z;
    const int zo = z / zdiv, zi = z % zdiv;
    in += (long long)z * inBatch;
    const long long ob = (long long)zo * outBO + (long long)zi * outBI;
    const int r0 = blockIdx.y * 32, c0 = blockIdx.x * 32;
    const int tx = threadIdx.x, ty = threadIdx.y;
#pragma unroll
    for (int i = 0; i < 4; i++)
        tile[ty + i * 8][tx] = in[(size_t)(r0 + ty + i * 8) * C + c0 + tx];
    __syncthreads();
#pragma unroll
    for (int i = 0; i < 4; i++) {
        const float v = tile[tx][ty + i * 8];
        bf h, l; bsplit(v, h, l);
        const long long o = ob + (long long)(c0 + ty + i * 8) * outLd + r0 + tx;
        oh[o] = h; ol[o] = l;
    }
}

__global__ void split_kernel(const float* __restrict__ in,
                             bf* __restrict__ oh, bf* __restrict__ ol, long long n)
{
    long long i = (long long)blockIdx.x * blockDim.x + threadIdx.x;
    const long long stride = (long long)gridDim.x * blockDim.x;
    for (; i < n; i += stride) {
        bf h, l; bsplit(in[i], h, l);
        oh[i] = h; ol[i] = l;
    }
}

// ---------------------------------------------------------------------------
// Masked softmax (in-place on d_out rows) + bf16 split planes
// ---------------------------------------------------------------------------
__global__ void softmax_kernel(float* __restrict__ attn,
                               bf* __restrict__ ah, bf* __restrict__ al,
                               const int* __restrict__ seq, int causal)
{
    const int q  = blockIdx.x;
    const int hb = blockIdx.y;
    const int b  = hb % NB;
    const size_t ro = ((size_t)hb * LT + q) * (size_t)LT;
    float* row = attn + ro;
    const int tid = threadIdx.x;
    const int s0 = tid, s1 = tid + 256;

    float v0 = row[s0];
    float v1 = row[s1];
    if ((causal && s0 > q) || seq[b * LS + s0] == 0) v0 = -INFINITY;
    if ((causal && s1 > q) || seq[b * LS + s1] == 0) v1 = -INFINITY;

    __shared__ float red[256];
    red[tid] = fmaxf(v0, v1);
    __syncthreads();
    for (int off = 128; off > 0; off >>= 1) {
        if (tid < off) red[tid] = fmaxf(red[tid], red[tid + off]);
        __syncthreads();
    }
    const float m = red[0];
    __syncthreads();

    const float e0 = expf(v0 - m);
    const float e1 = expf(v1 - m);
    red[tid] = e0 + e1;
    __syncthreads();
    for (int off = 128; off > 0; off >>= 1) {
        if (tid < off) red[tid] += red[tid + off];
        __syncthreads();
    }
    const float inv = 1.0f / red[0];
    const float p0 = e0 * inv, p1 = e1 * inv;
    row[s0] = p0; row[s1] = p1;
    bf h, l;
    bsplit(p0, h, l); ah[ro + s0] = h; al[ro + s0] = l;
    bsplit(p1, h, l); ah[ro + s1] = h; al[ro + s1] = l;
}

// ---------------------------------------------------------------------------
// x = LayerNorm(y + x) * g + b ; emit split planes
// ---------------------------------------------------------------------------
__global__ void add_ln_kernel(const float* __restrict__ y,
                              float* __restrict__ x,
                              bf* __restrict__ xh, bf* __restrict__ xl,
                              const float* __restrict__ g,
                              const float* __restrict__ b)
{
    const int t = blockIdx.x;
    const int tid = threadIdx.x;
    const float* yr = y + (size_t)t * D;
    float* xr = x + (size_t)t * D;

    const float v0 = yr[tid] + xr[tid];
    const float v1 = yr[tid + 256] + xr[tid + 256];

    __shared__ float red[256];
    red[tid] = v0 + v1;
    __syncthreads();
    for (int off = 128; off > 0; off >>= 1) {
        if (tid < off) red[tid] += red[tid + off];
        __syncthreads();
    }
    const float mu = red[0] * (1.0f / 512.0f);
    __syncthreads();

    const float d0 = v0 - mu;
    const float d1 = v1 - mu;
    red[tid] = d0 * d0 + d1 * d1;
    __syncthreads();
    for (int off = 128; off > 0; off >>= 1) {
        if (tid < off) red[tid] += red[tid + off];
        __syncthreads();
    }
    const float var = red[0] * (1.0f / 512.0f);
    const float sc = rsqrtf(var + 1e-5f);

    const float o0 = d0 * sc * g[tid] + b[tid];
    const float o1 = d1 * sc * g[tid + 256] + b[tid + 256];
    xr[tid] = o0; xr[tid + 256] = o1;
    bf h, l;
    bsplit(o0, h, l); xh[(size_t)t * D + tid] = h; xl[(size_t)t * D + tid] = l;
    bsplit(o1, h, l); xh[(size_t)t * D + tid + 256] = h; xl[(size_t)t * D + tid + 256] = l;
}

__global__ void embed_kernel(const int* __restrict__ seq,
                             const int* __restrict__ pos,
                             const float* __restrict__ wemb,
                             const float* __restrict__ pemb,
                             float* __restrict__ x,
                             bf* __restrict__ xh, bf* __restrict__ xl)
{
    const int t = blockIdx.x;
    const int tid = threadIdx.x;
    const size_t wo = (size_t)seq[t] * D;
    const size_t po = (size_t)pos[t] * D;
    const float v0 = wemb[wo + tid] + pemb[po + tid];
    const float v1 = wemb[wo + tid + 256] + pemb[po + tid + 256];
    x[(size_t)t * D + tid] = v0;
    x[(size_t)t * D + tid + 256] = v1;
    bf h, l;
    bsplit(v0, h, l); xh[(size_t)t * D + tid] = h; xl[(size_t)t * D + tid] = l;
    bsplit(v1, h, l); xh[(size_t)t * D + tid + 256] = h; xl[(size_t)t * D + tid + 256] = l;
}

__global__ void copy_kernel(const float* __restrict__ s, float* __restrict__ d,
                            long long n)
{
    long long i = (long long)blockIdx.x * blockDim.x + threadIdx.x;
    const long long stride = (long long)gridDim.x * blockDim.x;
    for (; i < n; i += stride) d[i] = s[i];
}

// ---------------------------------------------------------------------------
// Host side
// ---------------------------------------------------------------------------
struct GArgs {
    const bf *Ah, *Al; int lda; long long sAo, sAi;
    const bf *Bh, *Bl; int ldb; long long sBo, sBi;
    float* Cf; bf *Ch, *Cl; int ldc; long long sCo, sCi;
    int M, N, K, Z, zdiv; float alpha; const float* bias; int mode, relu;
};

constexpr int SMEM128 = 6 * 128 * 64 + 6 * 128 * 64;  // 98304
constexpr int SMEM64  = 6 * 128 * 64 + 6 * 64 * 64;   // 73728

static void g128(const GArgs& a) {
    dim3 grid(a.N / 128, a.M / 128, a.Z);
    gemm_bf3<128, 128, 64, 32><<<grid, 256, SMEM128>>>(
        a.Ah, a.Al, a.lda, a.sAo, a.sAi, a.Bh, a.Bl, a.ldb, a.sBo, a.sBi,
        a.Cf, a.Ch, a.Cl, a.ldc, a.sCo, a.sCi, a.K, a.zdiv, a.alpha, a.bias,
        a.mode, a.relu);
}
static void g64(const GArgs& a) {
    dim3 grid(a.N / 64, a.M / 128, a.Z);
    gemm_bf3<128, 64, 32, 32><<<grid, 256, SMEM64>>>(
        a.Ah, a.Al, a.lda, a.sAo, a.sAi, a.Bh, a.Bl, a.ldb, a.sBo, a.sBi,
        a.Cf, a.Ch, a.Cl, a.ldc, a.sCo, a.sCi, a.K, a.zdiv, a.alpha, a.bias,
        a.mode, a.relu);
}

extern "C" void kernel_launch(void* const* d_in, const int* in_sizes, int n_in,
                              void* d_out, int out_size)
{
    const int*   tgt_seq    = (const int*)  d_in[0];
    const int*   tgt_pos    = (const int*)  d_in[1];
    const int*   src_seq    = (const int*)  d_in[2];
    const float* enc_output = (const float*)d_in[3];
    const float* tgt_emb    = (const float*)d_in[4];
    const float* pos_emb    = (const float*)d_in[5];
    const float* slf_wq     = (const float*)d_in[6];
    const float* slf_wk     = (const float*)d_in[7];
    const float* slf_wv     = (const float*)d_in[8];
    const float* slf_pw     = (const float*)d_in[9];
    const float* slf_pb     = (const float*)d_in[10];
    const float* slf_g      = (const float*)d_in[11];
    const float* slf_b      = (const float*)d_in[12];
    const float* enc_wq     = (const float*)d_in[13];
    const float* enc_wk     = (const float*)d_in[14];
    const float* enc_wv     = (const float*)d_in[15];
    const float* enc_pw     = (const float*)d_in[16];
    const float* enc_pb     = (const float*)d_in[17];
    const float* enc_g      = (const float*)d_in[18];
    const float* enc_b      = (const float*)d_in[19];
    const float* ffn_w1     = (const float*)d_in[20];
    const float* ffn_b1     = (const float*)d_in[21];
    const float* ffn_w2     = (const float*)d_in[22];
    const float* ffn_b2     = (const float*)d_in[23];
    const float* ffn_g      = (const float*)d_in[24];
    const float* ffn_b      = (const float*)d_in[25];

    float* out = (float*)d_out;

    cudaFuncSetAttribute((const void*)gemm_bf3<128, 128, 64, 32>,
                         cudaFuncAttributeMaxDynamicSharedMemorySize, SMEM128);
    cudaFuncSetAttribute((const void*)gemm_bf3<128, 64, 32, 32>,
                         cudaFuncAttributeMaxDynamicSharedMemorySize, SMEM64);

    float *x, *y;
    cudaGetSymbolAddress((void**)&x, g_x);
    cudaGetSymbolAddress((void**)&y, g_y);
    auto sym = [](const void* s) {
        void* p; cudaGetSymbolAddress(&p, s); return (bf*)p;
    };
    bf *wsh = sym(g_wsh), *wsl = sym(g_wsl);
    bf *weh = sym(g_weh), *wel = sym(g_wel);
    bf *ph  = sym(g_ph),  *pl  = sym(g_pl);
    bf *f1h = sym(g_f1h), *f1l = sym(g_f1l);
    bf *f2h = sym(g_f2h), *f2l = sym(g_f2l);
    bf *xh = sym(g_xh), *xl = sym(g_xl);
    bf *eh = sym(g_eh), *el = sym(g_el);
    bf *qh = sym(g_qh), *ql = sym(g_ql);
    bf *kh = sym(g_kh), *kl = sym(g_kl);
    bf *vh = sym(g_vh), *vl = sym(g_vl);
    bf *ch = sym(g_ch), *cl = sym(g_cl);
    bf *hh = sym(g_hh), *hl = sym(g_hl);
    bf *ah = sym(g_ah), *al = sym(g_al);

    const float scale = 1.0f / sqrtf((float)D);
    const long long DD = (long long)D * D;

    // ---------- weight prep (batched across layers+heads) ----------
    split_kernel<<<2048, 256>>>(enc_output, eh, el, X_SIZE);
    const float* sW[3] = {slf_wq, slf_wk, slf_wv};
    const float* eW[3] = {enc_wq, enc_wk, enc_wv};
    for (int w = 0; w < 3; w++) {
        transpose_split<<<dim3(2, 16, NL * H), dim3(32, 8)>>>(
            sW[w], (long long)D * DK, DK,
            wsh + (long long)w * DD, wsl + (long long)w * DD,
            D, (long long)3 * DD, (long long)DK * D, H);
        transpose_split<<<dim3(2, 16, NL * H), dim3(32, 8)>>>(
            eW[w], (long long)D * DK, DK,
            weh + (long long)w * DD, wel + (long long)w * DD,
            D, (long long)3 * DD, (long long)DK * D, H);
    }
    transpose_split<<<dim3(16, 16, NL), dim3(32, 8)>>>(
        slf_pw, DD, D, ph, pl, D, 2 * DD, 0, 1);
    transpose_split<<<dim3(16, 16, NL), dim3(32, 8)>>>(
        enc_pw, DD, D, ph + DD, pl + DD, D, 2 * DD, 0, 1);
    transpose_split<<<dim3(64, 16, NL), dim3(32, 8)>>>(
        ffn_w1, (long long)D * DI, DI, f1h, f1l, D, (long long)DI * D, 0, 1);
    transpose_split<<<dim3(16, 64, NL), dim3(32, 8)>>>(
        ffn_w2, (long long)DI * D, D, f2h, f2l, DI, (long long)D * DI, 0, 1);

    embed_kernel<<<T, 256>>>(tgt_seq, tgt_pos, tgt_emb, pos_emb, x, xh, xl);

    const long long sAh_ = (long long)NB * LT * LT;
    const long long sAb_ = (long long)LT * LT;

    for (int l = 0; l < NL; l++) {
        for (int pass = 0; pass < 2; pass++) {
            const bool self = (pass == 0);
            const bf* Wh = (self ? wsh : weh) + (long long)l * 3 * DD;
            const bf* Wl = (self ? wsl : wel) + (long long)l * 3 * DD;
            const bf* inh = self ? xh : eh;
            const bf* inl = self ? xl : el;
            // Q (always from x)
            { GArgs a = {xh, xl, D, 0, 0, Wh, Wl, D, 0, 0,
                         nullptr, qh, ql, D, 0, 0, T, D, D, 1, 1, 1.f, nullptr, 1, 0};
              g128(a); }
            // K
            { GArgs a = {inh, inl, D, 0, 0, Wh + DD, Wl + DD, D, 0, 0,
                         nullptr, kh, kl, D, 0, 0, T, D, D, 1, 1, 1.f, nullptr, 1, 0};
              g128(a); }
            // V (transposed epilogue)
            { GArgs a = {inh, inl, D, 0, 0, Wh + 2 * DD, Wl + 2 * DD, D, 0, 0,
                         nullptr, vh, vl, 0, 0, 0, T, D, D, 1, 1, 1.f, nullptr, 2, 0};
              g128(a); }
            // scores -> d_out
            float* attn = out + (self ? SLF_OFF : ENC_OFF) + (long long)l * ATT;
            { GArgs a = {qh, ql, D, 64, sAb_, kh, kl, D, 64, sAb_,
                         attn, nullptr, nullptr, LT, sAh_, sAb_,
                         LT, LT, DK, H * NB, NB, scale, nullptr, 0, 0};
              g128(a); }
            softmax_kernel<<<dim3(LT, H * NB), 256>>>(
                attn, ah, al, self ? tgt_seq : src_seq, self ? 1 : 0);
            // AV -> ctx planes
            { GArgs a = {ah, al, LT, sAh_, sAb_, vh, vl, LT,
                         (long long)64 * 512, (long long)H * 64 * 512,
                         nullptr, ch, cl, D, 64, sAb_,
                         LT, DV, LT, H * NB, NB, 1.f, nullptr, 1, 0};
              g64(a); }
            // proj -> y (fp32)
            const bf* pwh = ph + ((long long)l * 2 + (self ? 0 : 1)) * DD;
            const bf* pwl = pl + ((long long)l * 2 + (self ? 0 : 1)) * DD;
            const float* pb = (self ? slf_pb : enc_pb) + (long long)l * D;
            { GArgs a = {ch, cl, D, 0, 0, pwh, pwl, D, 0, 0,
                         y, nullptr, nullptr, D, 0, 0, T, D, D, 1, 1, 1.f, pb, 0, 0};
              g128(a); }
            add_ln_kernel<<<T, 256>>>(y, x, xh, xl,
                (self ? slf_g : enc_g) + (long long)l * D,
                (self ? slf_b : enc_b) + (long long)l * D);
        }
        // FFN
        { GArgs a = {xh, xl, D, 0, 0, f1h + (long long)l * DI * D,
                     f1l + (long long)l * DI * D, D, 0, 0,
                     nullptr, hh, hl, DI, 0, 0, T, DI, D, 1, 1, 1.f,
                     ffn_b1 + (long long)l * DI, 1, 1};
          g128(a); }
        { GArgs a = {hh, hl, DI, 0, 0, f2h + (long long)l * D * DI,
                     f2l + (long long)l * D * DI, DI, 0, 0,
                     y, nullptr, nullptr, D, 0, 0, T, D, DI, 1, 1, 1.f,
                     ffn_b2 + (long long)l * D, 0, 0};
          g128(a); }
        add_ln_kernel<<<T, 256>>>(y, x, xh, xl,
            ffn_g + (long long)l * D, ffn_b + (long long)l * D);
    }

    copy_kernel<<<2048, 256>>>(x, out, X_SIZE);
}

// round 17
// speedup vs baseline: 2.5847x; 1.1693x over previous
#include <cuda_runtime.h>
#include <cuda_bf16.h>
#include <math.h>
#include <stdint.h>

// ---------------------------------------------------------------------------
// Problem constants
// ---------------------------------------------------------------------------
constexpr int NB  = 8;
constexpr int LT  = 512;
constexpr int LS  = 512;
constexpr int D   = 512;
constexpr int H   = 8;
constexpr int DK  = 64;
constexpr int DV  = 64;
constexpr int DI  = 2048;
constexpr int NL  = 6;
constexpr int T   = NB * LT;

constexpr long long X_SIZE  = (long long)T * D;
constexpr long long ATT     = (long long)H * NB * LT * LT;
constexpr long long SLF_OFF = X_SIZE;
constexpr long long ENC_OFF = X_SIZE + (long long)NL * ATT;

// ---------------------------------------------------------------------------
// Scratch
// ---------------------------------------------------------------------------
__device__ float g_x[T * D];
__device__ float g_y[T * D];

__device__ unsigned short g_wsh[NL * 3 * D * D], g_wsl[NL * 3 * D * D];
__device__ unsigned short g_weh[NL * 3 * D * D], g_wel[NL * 3 * D * D];
__device__ unsigned short g_ph [NL * 2 * D * D], g_pl [NL * 2 * D * D];
__device__ unsigned short g_f1h[NL * DI * D],    g_f1l[NL * DI * D];
__device__ unsigned short g_f2h[NL * D * DI],    g_f2l[NL * D * DI];

__device__ unsigned short g_xh[T * D], g_xl[T * D];
__device__ unsigned short g_eh[T * D], g_el[T * D];
__device__ unsigned short g_qh[T * D], g_ql[T * D];
__device__ unsigned short g_kh[T * D], g_kl[T * D];
__device__ unsigned short g_vh[T * D], g_vl[T * D];   // [b][h][e][s]
__device__ unsigned short g_ch[T * D], g_cl[T * D];
__device__ unsigned short g_hh[T * DI], g_hl[T * DI];

// ---------------------------------------------------------------------------
// Helpers
// ---------------------------------------------------------------------------
typedef __nv_bfloat16 bf;

__device__ __forceinline__ void bsplit(float v, bf& h, bf& l) {
    h = __float2bfloat16(v);
    l = __float2bfloat16(v - __bfloat162float(h));
}

__device__ __forceinline__ uint32_t pack2(bf a, bf b) {
    return (uint32_t)__bfloat16_as_ushort(a) |
           ((uint32_t)__bfloat16_as_ushort(b) << 16);
}

__device__ __forceinline__ void ldsm4(uint32_t* r, uint32_t addr) {
    asm volatile("ldmatrix.sync.aligned.m8n8.x4.shared.b16 {%0,%1,%2,%3}, [%4];"
        : "=r"(r[0]), "=r"(r[1]), "=r"(r[2]), "=r"(r[3]) : "r"(addr));
}

__device__ __forceinline__ void mma_bf16(float* d, const uint32_t* a,
                                         uint32_t b0, uint32_t b1) {
    asm volatile(
        "mma.sync.aligned.m16n8k16.row.col.f32.bf16.bf16.f32 "
        "{%0,%1,%2,%3},{%4,%5,%6,%7},{%8,%9},{%0,%1,%2,%3};"
        : "+f"(d[0]), "+f"(d[1]), "+f"(d[2]), "+f"(d[3])
        : "r"(a[0]), "r"(a[1]), "r"(a[2]), "r"(a[3]), "r"(b0), "r"(b1));
}

__device__ __forceinline__ void cpasync16(uint32_t saddr, const void* g) {
    asm volatile("cp.async.cg.shared.global [%0], [%1], 16;" :: "r"(saddr), "l"(g));
}
__device__ __forceinline__ void cp_commit() { asm volatile("cp.async.commit_group;"); }
template<int N> __device__ __forceinline__ void cp_wait() {
    asm volatile("cp.async.wait_group %0;" :: "n"(N));
}

// swizzled smem byte offset for (row r of 64B, 16B-unit u)
__device__ __forceinline__ uint32_t swz(int r, int u) {
    return (uint32_t)((r << 6) + ((u ^ ((r >> 1) & 3)) << 4));
}

// ---------------------------------------------------------------------------
// bf16 3-product GEMM (mma.sync)
// ---------------------------------------------------------------------------
template<int BM, int BN, int WM, int WN>
__global__ __launch_bounds__(256, 1) void gemm_bf3(
    const bf* __restrict__ Ah, const bf* __restrict__ Al,
    int lda, long long sAo, long long sAi,
    const bf* __restrict__ Bh, const bf* __restrict__ Bl,
    int ldb, long long sBo, long long sBi,
    float* __restrict__ Cf, bf* __restrict__ Ch, bf* __restrict__ Cl,
    int ldc, long long sCo, long long sCi,
    int K, int zdiv, float alpha, const float* __restrict__ bias,
    int mode, int relu)
{
    constexpr int MT = WM / 16;
    constexpr int NT = WN / 8;
    constexpr int NP = WN / 16;
    constexpr int WCOL = BN / WN;
    constexpr int ABYTES = BM * 64;
    constexpr int BBYTES = BN * 64;

    extern __shared__ uint8_t smem[];
    const uint32_t sbase = (uint32_t)__cvta_generic_to_shared(smem);

    const int zo = blockIdx.z / zdiv;
    const int zi = blockIdx.z % zdiv;
    Ah += zo * sAo + zi * sAi;  Al += zo * sAo + zi * sAi;
    Bh += zo * sBo + zi * sBi;  Bl += zo * sBo + zi * sBi;
    const long long cOff = zo * sCo + zi * sCi;

    const int m0 = blockIdx.y * BM;
    const int n0 = blockIdx.x * BN;
    const int tid  = threadIdx.x;
    const int warp = tid >> 5, lane = tid & 31;
    const int wm = (warp / WCOL) * WM;
    const int wn = (warp % WCOL) * WN;

    float acc[MT][NT][4];
#pragma unroll
    for (int i = 0; i < MT; i++)
#pragma unroll
        for (int j = 0; j < NT; j++)
#pragma unroll
            for (int e = 0; e < 4; e++) acc[i][j][e] = 0.f;

    auto sA = [&](int buf, int p) { return sbase + (uint32_t)((buf * 2 + p) * ABYTES); };
    auto sB = [&](int buf, int p) { return sbase + (uint32_t)(6 * ABYTES + (buf * 2 + p) * BBYTES); };

    auto load_chunk = [&](int k0, int buf) {
#pragma unroll
        for (int p = 0; p < 2; p++) {
            const bf* src = p ? Al : Ah;
#pragma unroll
            for (int i = 0; i < BM / 64; i++) {
                const int idx = tid + i * 256;
                const int r = idx >> 2, u = idx & 3;
                cpasync16(sA(buf, p) + swz(r, u),
                          src + (size_t)(m0 + r) * lda + k0 + u * 8);
            }
        }
#pragma unroll
        for (int p = 0; p < 2; p++) {
            const bf* src = p ? Bl : Bh;
#pragma unroll
            for (int i = 0; i < BN / 64; i++) {
                const int idx = tid + i * 256;
                const int r = idx >> 2, u = idx & 3;
                cpasync16(sB(buf, p) + swz(r, u),
                          src + (size_t)(n0 + r) * ldb + k0 + u * 8);
            }
        }
        cp_commit();
    };

    auto compute = [&](int buf) {
#pragma unroll
        for (int ub = 0; ub < 4; ub += 2) {
            uint32_t a[2][MT][4];
#pragma unroll
            for (int p = 0; p < 2; p++)
#pragma unroll
                for (int mt = 0; mt < MT; mt++)
                    ldsm4(a[p][mt], sA(buf, p) +
                          swz(wm + mt * 16 + (lane & 15), ub + (lane >> 4)));
            uint32_t b[2][NP][4];
#pragma unroll
            for (int p = 0; p < 2; p++)
#pragma unroll
                for (int pr = 0; pr < NP; pr++)
                    ldsm4(b[p][pr], sB(buf, p) +
                          swz(wn + pr * 16 + ((lane & 16) >> 1) + (lane & 7),
                              ub + ((lane >> 3) & 1)));
#pragma unroll
            for (int nt = 0; nt < NT; nt++) {
                const int pr = nt >> 1, o = (nt & 1) * 2;
                const uint32_t bh0 = b[0][pr][o], bh1 = b[0][pr][o + 1];
                const uint32_t bl0 = b[1][pr][o], bl1 = b[1][pr][o + 1];
#pragma unroll
                for (int mt = 0; mt < MT; mt++) {
                    mma_bf16(acc[mt][nt], a[0][mt], bh0, bh1);
                    mma_bf16(acc[mt][nt], a[0][mt], bl0, bl1);
                    mma_bf16(acc[mt][nt], a[1][mt], bh0, bh1);
                }
            }
        }
    };

    const int NC = K / 32;
    load_chunk(0, 0);
    if (NC > 1) load_chunk(32, 1);
    for (int c = 0; c < NC; c++) {
        if (c + 1 < NC) cp_wait<1>(); else cp_wait<0>();
        __syncthreads();
        if (c + 2 < NC) load_chunk((c + 2) * 32, (c + 2) % 3);
        compute(c % 3);
    }

    const int g = lane >> 2, c2 = (lane & 3) * 2;
#pragma unroll
    for (int mt = 0; mt < MT; mt++) {
#pragma unroll
        for (int nt = 0; nt < NT; nt++) {
            const int mA = m0 + wm + mt * 16 + g;
            const int nA = n0 + wn + nt * 8 + c2;
            float b0 = 0.f, b1 = 0.f;
            if (bias) { b0 = bias[nA]; b1 = bias[nA + 1]; }
            float v0 = acc[mt][nt][0] * alpha + b0;
            float v1 = acc[mt][nt][1] * alpha + b1;
            float v2 = acc[mt][nt][2] * alpha + b0;
            float v3 = acc[mt][nt][3] * alpha + b1;
            if (relu) {
                v0 = fmaxf(v0, 0.f); v1 = fmaxf(v1, 0.f);
                v2 = fmaxf(v2, 0.f); v3 = fmaxf(v3, 0.f);
            }
            if (mode == 0) {
                float2 p0 = {v0, v1}, p1 = {v2, v3};
                *reinterpret_cast<float2*>(Cf + cOff + (size_t)mA * ldc + nA) = p0;
                *reinterpret_cast<float2*>(Cf + cOff + (size_t)(mA + 8) * ldc + nA) = p1;
            } else if (mode == 1) {
                bf h0, l0, h1, l1, h2, l2, h3, l3;
                bsplit(v0, h0, l0); bsplit(v1, h1, l1);
                bsplit(v2, h2, l2); bsplit(v3, h3, l3);
                __nv_bfloat162 ph0; ph0.x = h0; ph0.y = h1;
                __nv_bfloat162 pl0; pl0.x = l0; pl0.y = l1;
                __nv_bfloat162 ph1; ph1.x = h2; ph1.y = h3;
                __nv_bfloat162 pl1; pl1.x = l2; pl1.y = l3;
                *reinterpret_cast<__nv_bfloat162*>(Ch + cOff + (size_t)mA * ldc + nA) = ph0;
                *reinterpret_cast<__nv_bfloat162*>(Cl + cOff + (size_t)mA * ldc + nA) = pl0;
                *reinterpret_cast<__nv_bfloat162*>(Ch + cOff + (size_t)(mA + 8) * ldc + nA) = ph1;
                *reinterpret_cast<__nv_bfloat162*>(Cl + cOff + (size_t)(mA + 8) * ldc + nA) = pl1;
            } else {
                auto st = [&](int t, int nn, float val) {
                    bf hh, ll; bsplit(val, hh, ll);
                    const size_t idx = (size_t)(t >> 9) * (H * 64 * 512)
                                     + (size_t)(nn >> 6) * (64 * 512)
                                     + (size_t)(nn & 63) * 512 + (t & 511);
                    Ch[idx] = hh; Cl[idx] = ll;
                };
                st(mA, nA, v0); st(mA, nA + 1, v1);
                st(mA + 8, nA, v2); st(mA + 8, nA + 1, v3);
            }
        }
    }
}

// ---------------------------------------------------------------------------
// Fused attention: scores + masked softmax + AV, one CTA per (hb, q-block 128)
// ---------------------------------------------------------------------------
__global__ __launch_bounds__(256, 1) void fused_attn(
    const bf* __restrict__ qh, const bf* __restrict__ ql,
    const bf* __restrict__ kh, const bf* __restrict__ kl,
    const bf* __restrict__ vh, const bf* __restrict__ vl,
    float* __restrict__ attn,
    bf* __restrict__ ch, bf* __restrict__ cl,
    const int* __restrict__ seq, int causal, float scale)
{
    const int q0 = blockIdx.x * 128;
    const int hb = blockIdx.y;
    const int h = hb / NB, b = hb % NB;
    const int tid = threadIdx.x, warp = tid >> 5, lane = tid & 31;
    const int g = lane >> 2, c = lane & 3;
    const int wm = warp * 16;

    extern __shared__ uint8_t smem[];
    uint8_t* mflag = smem;
    const uint32_t sb = (uint32_t)__cvta_generic_to_shared(smem);
    const uint32_t sQ = sb + 1024;
    auto sQa = [&](int kc, int p) { return sQ + (uint32_t)((kc * 2 + p) * 8192); };
    const uint32_t sKV = sb + 1024 + 32768;
    auto sK = [&](int buf, int kc, int p) {
        return sKV + (uint32_t)(buf * 32768 + (kc * 2 + p) * 8192);
    };
    auto sV = [&](int buf, int ci, int p) {
        return sKV + (uint32_t)(buf * 32768 + (ci * 2 + p) * 4096);
    };

    for (int i = tid; i < 512; i += 256) mflag[i] = (seq[b * LS + i] == 0) ? 1 : 0;

#pragma unroll
    for (int kc = 0; kc < 2; kc++)
#pragma unroll
        for (int p = 0; p < 2; p++) {
            const bf* src = p ? ql : qh;
#pragma unroll
            for (int i = 0; i < 2; i++) {
                const int idx = tid + i * 256;
                const int r = idx >> 2, u = idx & 3;
                cpasync16(sQa(kc, p) + swz(r, u),
                          src + (size_t)(b * 512 + q0 + r) * D + h * 64 + kc * 32 + u * 8);
            }
        }
    auto loadK = [&](int st, int buf) {
#pragma unroll
        for (int kc = 0; kc < 2; kc++)
#pragma unroll
            for (int p = 0; p < 2; p++) {
                const bf* src = p ? kl : kh;
#pragma unroll
                for (int i = 0; i < 2; i++) {
                    const int idx = tid + i * 256;
                    const int r = idx >> 2, u = idx & 3;
                    cpasync16(sK(buf, kc, p) + swz(r, u),
                              src + (size_t)(b * 512 + st * 128 + r) * D + h * 64 + kc * 32 + u * 8);
                }
            }
        cp_commit();
    };
    loadK(0, 0);
    cp_wait<0>();
    __syncthreads();

    uint32_t qa[2][2][2][4];
#pragma unroll
    for (int kc = 0; kc < 2; kc++)
#pragma unroll
        for (int ubi = 0; ubi < 2; ubi++)
#pragma unroll
            for (int p = 0; p < 2; p++)
                ldsm4(qa[kc][ubi][p],
                      sQa(kc, p) + swz(wm + (lane & 15), ubi * 2 + (lane >> 4)));

    const size_t abase = (size_t)hb * 512 * 512;
    float m0 = -INFINITY, m1 = -INFINITY, l0 = 0.f, l1 = 0.f;

    for (int st = 0; st < 4; st++) {
        if (st + 1 < 4) loadK(st + 1, (st + 1) & 1);
        const int buf = st & 1;

        float acc[16][4];
#pragma unroll
        for (int nt = 0; nt < 16; nt++)
#pragma unroll
            for (int e = 0; e < 4; e++) acc[nt][e] = 0.f;

#pragma unroll
        for (int kc = 0; kc < 2; kc++)
#pragma unroll
            for (int ubi = 0; ubi < 2; ubi++) {
#pragma unroll
                for (int pr = 0; pr < 8; pr++) {
                    uint32_t kbh[4], kbl[4];
                    ldsm4(kbh, sK(buf, kc, 0) +
                          swz(pr * 16 + ((lane & 16) >> 1) + (lane & 7),
                              ubi * 2 + ((lane >> 3) & 1)));
                    ldsm4(kbl, sK(buf, kc, 1) +
                          swz(pr * 16 + ((lane & 16) >> 1) + (lane & 7),
                              ubi * 2 + ((lane >> 3) & 1)));
#pragma unroll
                    for (int half = 0; half < 2; half++) {
                        const int nt = pr * 2 + half, o = half * 2;
                        mma_bf16(acc[nt], qa[kc][ubi][0], kbh[o], kbh[o + 1]);
                        mma_bf16(acc[nt], qa[kc][ubi][0], kbl[o], kbl[o + 1]);
                        mma_bf16(acc[nt], qa[kc][ubi][1], kbh[o], kbh[o + 1]);
                    }
                }
            }

        const int row0 = q0 + wm + g, row1 = row0 + 8;
#pragma unroll
        for (int nt = 0; nt < 16; nt++) {
            const int s0c = st * 128 + nt * 8 + 2 * c;
#pragma unroll
            for (int e = 0; e < 4; e++) {
                const int s = s0c + (e & 1);
                const int row = (e >= 2) ? row1 : row0;
                if ((causal && s > row) || mflag[s]) acc[nt][e] = -INFINITY;
                else acc[nt][e] *= scale;
            }
        }

        float tm0 = -INFINITY, tm1 = -INFINITY;
#pragma unroll
        for (int nt = 0; nt < 16; nt++) {
            tm0 = fmaxf(tm0, fmaxf(acc[nt][0], acc[nt][1]));
            tm1 = fmaxf(tm1, fmaxf(acc[nt][2], acc[nt][3]));
        }
        tm0 = fmaxf(tm0, __shfl_xor_sync(0xffffffffu, tm0, 1));
        tm0 = fmaxf(tm0, __shfl_xor_sync(0xffffffffu, tm0, 2));
        tm1 = fmaxf(tm1, __shfl_xor_sync(0xffffffffu, tm1, 1));
        tm1 = fmaxf(tm1, __shfl_xor_sync(0xffffffffu, tm1, 2));

        const float nm0 = fmaxf(m0, tm0), nm1 = fmaxf(m1, tm1);
        float su0 = 0.f, su1 = 0.f;
        if (nm0 > -INFINITY) {
#pragma unroll
            for (int nt = 0; nt < 16; nt++) {
                su0 += expf(acc[nt][0] - nm0) + expf(acc[nt][1] - nm0);
            }
        }
        if (nm1 > -INFINITY) {
#pragma unroll
            for (int nt = 0; nt < 16; nt++) {
                su1 += expf(acc[nt][2] - nm1) + expf(acc[nt][3] - nm1);
            }
        }
        su0 += __shfl_xor_sync(0xffffffffu, su0, 1);
        su0 += __shfl_xor_sync(0xffffffffu, su0, 2);
        su1 += __shfl_xor_sync(0xffffffffu, su1, 1);
        su1 += __shfl_xor_sync(0xffffffffu, su1, 2);

        const float sf0 = (l0 == 0.f) ? 0.f : expf(m0 - nm0);
        const float sf1 = (l1 == 0.f) ? 0.f : expf(m1 - nm1);
        l0 = l0 * sf0 + su0;  m0 = nm0;
        l1 = l1 * sf1 + su1;  m1 = nm1;

#pragma unroll
        for (int nt = 0; nt < 16; nt++) {
            const int colb = st * 128 + nt * 8 + 2 * c;
            float2 p0 = {acc[nt][0], acc[nt][1]};
            float2 p1 = {acc[nt][2], acc[nt][3]};
            *reinterpret_cast<float2*>(attn + abase + (size_t)row0 * 512 + colb) = p0;
            *reinterpret_cast<float2*>(attn + abase + (size_t)row1 * 512 + colb) = p1;
        }

        if (st + 1 < 4) { cp_wait<0>(); __syncthreads(); }
    }

    const float invl0 = 1.f / l0, invl1 = 1.f / l1;

    __syncthreads();
    auto loadV = [&](int st, int buf) {
#pragma unroll
        for (int ci = 0; ci < 4; ci++)
#pragma unroll
            for (int p = 0; p < 2; p++) {
                const bf* src = p ? vl : vh;
                const int r = tid >> 2, u = tid & 3;
                cpasync16(sV(buf, ci, p) + swz(r, u),
                          src + (size_t)b * (H * 64 * 512) + (size_t)h * (64 * 512)
                              + (size_t)r * 512 + st * 128 + ci * 32 + u * 8);
            }
        cp_commit();
    };
    loadV(0, 0);
    cp_wait<0>();
    __syncthreads();

    float accv[8][4];
#pragma unroll
    for (int nt = 0; nt < 8; nt++)
#pragma unroll
        for (int e = 0; e < 4; e++) accv[nt][e] = 0.f;

    const int row0 = q0 + wm + g, row1 = row0 + 8;
    for (int st = 0; st < 4; st++) {
        if (st + 1 < 4) loadV(st + 1, (st + 1) & 1);
        const int buf = st & 1;

#pragma unroll
        for (int kk = 0; kk < 8; kk++) {
            const int ci = kk >> 1, ubo = (kk & 1) * 2;
            const int col0 = st * 128 + kk * 16 + 2 * c;

            float* a0p = attn + abase + (size_t)row0 * 512 + col0;
            float* a1p = attn + abase + (size_t)row1 * 512 + col0;
            float2 r0a = *reinterpret_cast<float2*>(a0p);
            float2 r0b = *reinterpret_cast<float2*>(a0p + 8);
            float2 r1a = *reinterpret_cast<float2*>(a1p);
            float2 r1b = *reinterpret_cast<float2*>(a1p + 8);

            r0a.x = expf(r0a.x - m0) * invl0;  r0a.y = expf(r0a.y - m0) * invl0;
            r0b.x = expf(r0b.x - m0) * invl0;  r0b.y = expf(r0b.y - m0) * invl0;
            r1a.x = expf(r1a.x - m1) * invl1;  r1a.y = expf(r1a.y - m1) * invl1;
            r1b.x = expf(r1b.x - m1) * invl1;  r1b.y = expf(r1b.y - m1) * invl1;

            *reinterpret_cast<float2*>(a0p)     = r0a;
            *reinterpret_cast<float2*>(a0p + 8) = r0b;
            *reinterpret_cast<float2*>(a1p)     = r1a;
            *reinterpret_cast<float2*>(a1p + 8) = r1b;

            bf h0, lo0, h1, lo1;
            uint32_t ahi[4], alo[4];
            bsplit(r0a.x, h0, lo0); bsplit(r0a.y, h1, lo1);
            ahi[0] = pack2(h0, h1); alo[0] = pack2(lo0, lo1);
            bsplit(r1a.x, h0, lo0); bsplit(r1a.y, h1, lo1);
            ahi[1] = pack2(h0, h1); alo[1] = pack2(lo0, lo1);
            bsplit(r0b.x, h0, lo0); bsplit(r0b.y, h1, lo1);
            ahi[2] = pack2(h0, h1); alo[2] = pack2(lo0, lo1);
            bsplit(r1b.x, h0, lo0); bsplit(r1b.y, h1, lo1);
            ahi[3] = pack2(h0, h1); alo[3] = pack2(lo0, lo1);

#pragma unroll
            for (int pr = 0; pr < 4; pr++) {
                uint32_t vbh[4], vbl[4];
                ldsm4(vbh, sV(buf, ci, 0) +
                      swz(pr * 16 + ((lane & 16) >> 1) + (lane & 7),
                          ubo + ((lane >> 3) & 1)));
                ldsm4(vbl, sV(buf, ci, 1) +
                      swz(pr * 16 + ((lane & 16) >> 1) + (lane & 7),
                          ubo + ((lane >> 3) & 1)));
#pragma unroll
                for (int half = 0; half < 2; half++) {
                    const int nt = pr * 2 + half, o = half * 2;
                    mma_bf16(accv[nt], ahi, vbh[o], vbh[o + 1]);
                    mma_bf16(accv[nt], ahi, vbl[o], vbl[o + 1]);
                    mma_bf16(accv[nt], alo, vbh[o], vbh[o + 1]);
                }
            }
        }

        if (st + 1 < 4) { cp_wait<0>(); __syncthreads(); }
    }

#pragma unroll
    for (int nt = 0; nt < 8; nt++) {
        const int col = h * 64 + nt * 8 + 2 * c;
        bf h0, l0b, h1, l1b;
        bsplit(accv[nt][0], h0, l0b); bsplit(accv[nt][1], h1, l1b);
        __nv_bfloat162 ph; ph.x = h0; ph.y = h1;
        __nv_bfloat162 pl; pl.x = l0b; pl.y = l1b;
        *reinterpret_cast<__nv_bfloat162*>(ch + (size_t)(b * 512 + row0) * D + col) = ph;
        *reinterpret_cast<__nv_bfloat162*>(cl + (size_t)(b * 512 + row0) * D + col) = pl;
        bsplit(accv[nt][2], h0, l0b); bsplit(accv[nt][3], h1, l1b);
        ph.x = h0; ph.y = h1; pl.x = l0b; pl.y = l1b;
        *reinterpret_cast<__nv_bfloat162*>(ch + (size_t)(b * 512 + row1) * D + col) = ph;
        *reinterpret_cast<__nv_bfloat162*>(cl + (size_t)(b * 512 + row1) * D + col) = pl;
    }
}

// ---------------------------------------------------------------------------
// Transposed split with (zo, zi) batching
// ---------------------------------------------------------------------------
__global__ void transpose_split(const float* __restrict__ in, long long inBatch,
                                int C, bf* __restrict__ oh, bf* __restrict__ ol,
                                int outLd, long long outBO, long long outBI,
                                int zdiv)
{
    __shared__ float tile[32][33];
    const int z = blockIdx.z;
    const int zo = z / zdiv, zi = z % zdiv;
    in += (long long)z * inBatch;
    const long long ob = (long long)zo * outBO + (long long)zi * outBI;
    const int r0 = blockIdx.y * 32, c0 = blockIdx.x * 32;
    const int tx = threadIdx.x, ty = threadIdx.y;
#pragma unroll
    for (int i = 0; i < 4; i++)
        tile[ty + i * 8][tx] = in[(size_t)(r0 + ty + i * 8) * C + c0 + tx];
    __syncthreads();
#pragma unroll
    for (int i = 0; i < 4; i++) {
        const float v = tile[tx][ty + i * 8];
        bf h, l; bsplit(v, h, l);
        const long long o = ob + (long long)(c0 + ty + i * 8) * outLd + r0 + tx;
        oh[o] = h; ol[o] = l;
    }
}

__global__ void split_kernel(const float* __restrict__ in,
                             bf* __restrict__ oh, bf* __restrict__ ol, long long n)
{
    long long i = (long long)blockIdx.x * blockDim.x + threadIdx.x;
    const long long stride = (long long)gridDim.x * blockDim.x;
    for (; i < n; i += stride) {
        bf h, l; bsplit(in[i], h, l);
        oh[i] = h; ol[i] = l;
    }
}

// ---------------------------------------------------------------------------
// x = LayerNorm(y + x) * g + b ; emit split planes
// ---------------------------------------------------------------------------
__global__ void add_ln_kernel(const float* __restrict__ y,
                              float* __restrict__ x,
                              bf* __restrict__ xh, bf* __restrict__ xl,
                              const float* __restrict__ g,
                              const float* __restrict__ b)
{
    const int t = blockIdx.x;
    const int tid = threadIdx.x;
    const float* yr = y + (size_t)t * D;
    float* xr = x + (size_t)t * D;

    const float v0 = yr[tid] + xr[tid];
    const float v1 = yr[tid + 256] + xr[tid + 256];

    __shared__ float red[256];
    red[tid] = v0 + v1;
    __syncthreads();
    for (int off = 128; off > 0; off >>= 1) {
        if (tid < off) red[tid] += red[tid + off];
        __syncthreads();
    }
    const float mu = red[0] * (1.0f / 512.0f);
    __syncthreads();

    const float d0 = v0 - mu;
    const float d1 = v1 - mu;
    red[tid] = d0 * d0 + d1 * d1;
    __syncthreads();
    for (int off = 128; off > 0; off >>= 1) {
        if (tid < off) red[tid] += red[tid + off];
        __syncthreads();
    }
    const float var = red[0] * (1.0f / 512.0f);
    const float sc = rsqrtf(var + 1e-5f);

    const float o0 = d0 * sc * g[tid] + b[tid];
    const float o1 = d1 * sc * g[tid + 256] + b[tid + 256];
    xr[tid] = o0; xr[tid + 256] = o1;
    bf h, l;
    bsplit(o0, h, l); xh[(size_t)t * D + tid] = h; xl[(size_t)t * D + tid] = l;
    bsplit(o1, h, l); xh[(size_t)t * D + tid + 256] = h; xl[(size_t)t * D + tid + 256] = l;
}

__global__ void embed_kernel(const int* __restrict__ seq,
                             const int* __restrict__ pos,
                             const float* __restrict__ wemb,
                             const float* __restrict__ pemb,
                             float* __restrict__ x,
                             bf* __restrict__ xh, bf* __restrict__ xl)
{
    const int t = blockIdx.x;
    const int tid = threadIdx.x;
    const size_t wo = (size_t)seq[t] * D;
    const size_t po = (size_t)pos[t] * D;
    const float v0 = wemb[wo + tid] + pemb[po + tid];
    const float v1 = wemb[wo + tid + 256] + pemb[po + tid + 256];
    x[(size_t)t * D + tid] = v0;
    x[(size_t)t * D + tid + 256] = v1;
    bf h, l;
    bsplit(v0, h, l); xh[(size_t)t * D + tid] = h; xl[(size_t)t * D + tid] = l;
    bsplit(v1, h, l); xh[(size_t)t * D + tid + 256] = h; xl[(size_t)t * D + tid + 256] = l;
}

__global__ void copy_kernel(const float* __restrict__ s, float* __restrict__ d,
                            long long n)
{
    long long i = (long long)blockIdx.x * blockDim.x + threadIdx.x;
    const long long stride = (long long)gridDim.x * blockDim.x;
    for (; i < n; i += stride) d[i] = s[i];
}

// ---------------------------------------------------------------------------
// Host side
// ---------------------------------------------------------------------------
struct GArgs {
    const bf *Ah, *Al; int lda; long long sAo, sAi;
    const bf *Bh, *Bl; int ldb; long long sBo, sBi;
    float* Cf; bf *Ch, *Cl; int ldc; long long sCo, sCi;
    int M, N, K, Z, zdiv; float alpha; const float* bias; int mode, relu;
};

constexpr int SMEM128 = 6 * 128 * 64 + 6 * 128 * 64;  // 98304
constexpr int SMEM_FA = 1024 + 32768 + 65536;         // 99328

static void g128(const GArgs& a) {
    dim3 grid(a.N / 128, a.M / 128, a.Z);
    gemm_bf3<128, 128, 64, 32><<<grid, 256, SMEM128>>>(
        a.Ah, a.Al, a.lda, a.sAo, a.sAi, a.Bh, a.Bl, a.ldb, a.sBo, a.sBi,
        a.Cf, a.Ch, a.Cl, a.ldc, a.sCo, a.sCi, a.K, a.zdiv, a.alpha, a.bias,
        a.mode, a.relu);
}

extern "C" void kernel_launch(void* const* d_in, const int* in_sizes, int n_in,
                              void* d_out, int out_size)
{
    const int*   tgt_seq    = (const int*)  d_in[0];
    const int*   tgt_pos    = (const int*)  d_in[1];
    const int*   src_seq    = (const int*)  d_in[2];
    const float* enc_output = (const float*)d_in[3];
    const float* tgt_emb    = (const float*)d_in[4];
    const float* pos_emb    = (const float*)d_in[5];
    const float* slf_wq     = (const float*)d_in[6];
    const float* slf_wk     = (const float*)d_in[7];
    const float* slf_wv     = (const float*)d_in[8];
    const float* slf_pw     = (const float*)d_in[9];
    const float* slf_pb     = (const float*)d_in[10];
    const float* slf_g      = (const float*)d_in[11];
    const float* slf_b      = (const float*)d_in[12];
    const float* enc_wq     = (const float*)d_in[13];
    const float* enc_wk     = (const float*)d_in[14];
    const float* enc_wv     = (const float*)d_in[15];
    const float* enc_pw     = (const float*)d_in[16];
    const float* enc_pb     = (const float*)d_in[17];
    const float* enc_g      = (const float*)d_in[18];
    const float* enc_b      = (const float*)d_in[19];
    const float* ffn_w1     = (const float*)d_in[20];
    const float* ffn_b1     = (const float*)d_in[21];
    const float* ffn_w2     = (const float*)d_in[22];
    const float* ffn_b2     = (const float*)d_in[23];
    const float* ffn_g      = (const float*)d_in[24];
    const float* ffn_b      = (const float*)d_in[25];

    float* out = (float*)d_out;

    cudaFuncSetAttribute((const void*)gemm_bf3<128, 128, 64, 32>,
                         cudaFuncAttributeMaxDynamicSharedMemorySize, SMEM128);
    cudaFuncSetAttribute((const void*)fused_attn,
                         cudaFuncAttributeMaxDynamicSharedMemorySize, SMEM_FA);

    float *x, *y;
    cudaGetSymbolAddress((void**)&x, g_x);
    cudaGetSymbolAddress((void**)&y, g_y);
    auto sym = [](const void* s) {
        void* p; cudaGetSymbolAddress(&p, s); return (bf*)p;
    };
    bf *wsh = sym(g_wsh), *wsl = sym(g_wsl);
    bf *weh = sym(g_weh), *wel = sym(g_wel);
    bf *ph  = sym(g_ph),  *pl  = sym(g_pl);
    bf *f1h = sym(g_f1h), *f1l = sym(g_f1l);
    bf *f2h = sym(g_f2h), *f2l = sym(g_f2l);
    bf *xh = sym(g_xh), *xl = sym(g_xl);
    bf *eh = sym(g_eh), *el = sym(g_el);
    bf *qh = sym(g_qh), *ql = sym(g_ql);
    bf *kh = sym(g_kh), *kl = sym(g_kl);
    bf *vh = sym(g_vh), *vl = sym(g_vl);
    bf *ch = sym(g_ch), *cl = sym(g_cl);
    bf *hh = sym(g_hh), *hl = sym(g_hl);

    const float scale = 1.0f / sqrtf((float)D);
    const long long DD = (long long)D * D;

    // ---------- weight prep ----------
    split_kernel<<<2048, 256>>>(enc_output, eh, el, X_SIZE);
    const float* sW[3] = {slf_wq, slf_wk, slf_wv};
    const float* eW[3] = {enc_wq, enc_wk, enc_wv};
    for (int w = 0; w < 3; w++) {
        transpose_split<<<dim3(2, 16, NL * H), dim3(32, 8)>>>(
            sW[w], (long long)D * DK, DK,
            wsh + (long long)w * DD, wsl + (long long)w * DD,
            D, (long long)3 * DD, (long long)DK * D, H);
        transpose_split<<<dim3(2, 16, NL * H), dim3(32, 8)>>>(
            eW[w], (long long)D * DK, DK,
            weh + (long long)w * DD, wel + (long long)w * DD,
            D, (long long)3 * DD, (long long)DK * D, H);
    }
    transpose_split<<<dim3(16, 16, NL), dim3(32, 8)>>>(
        slf_pw, DD, D, ph, pl, D, 2 * DD, 0, 1);
    transpose_split<<<dim3(16, 16, NL), dim3(32, 8)>>>(
        enc_pw, DD, D, ph + DD, pl + DD, D, 2 * DD, 0, 1);
    transpose_split<<<dim3(64, 16, NL), dim3(32, 8)>>>(
        ffn_w1, (long long)D * DI, DI, f1h, f1l, D, (long long)DI * D, 0, 1);
    transpose_split<<<dim3(16, 64, NL), dim3(32, 8)>>>(
        ffn_w2, (long long)DI * D, D, f2h, f2l, DI, (long long)D * DI, 0, 1);

    embed_kernel<<<T, 256>>>(tgt_seq, tgt_pos, tgt_emb, pos_emb, x, xh, xl);

    for (int l = 0; l < NL; l++) {
        for (int pass = 0; pass < 2; pass++) {
            const bool self = (pass == 0);
            const bf* Wh = (self ? wsh : weh) + (long long)l * 3 * DD;
            const bf* Wl = (self ? wsl : wel) + (long long)l * 3 * DD;
            const bf* inh = self ? xh : eh;
            const bf* inl = self ? xl : el;
            // Q (always from x)
            { GArgs a = {xh, xl, D, 0, 0, Wh, Wl, D, 0, 0,
                         nullptr, qh, ql, D, 0, 0, T, D, D, 1, 1, 1.f, nullptr, 1, 0};
              g128(a); }
            // K
            { GArgs a = {inh, inl, D, 0, 0, Wh + DD, Wl + DD, D, 0, 0,
                         nullptr, kh, kl, D, 0, 0, T, D, D, 1, 1, 1.f, nullptr, 1, 0};
              g128(a); }
            // V (transposed epilogue)
            { GArgs a = {inh, inl, D, 0, 0, Wh + 2 * DD, Wl + 2 * DD, D, 0, 0,
                         nullptr, vh, vl, 0, 0, 0, T, D, D, 1, 1, 1.f, nullptr, 2, 0};
              g128(a); }
            // fused attention
            float* attn = out + (self ? SLF_OFF : ENC_OFF) + (long long)l * ATT;
            fused_attn<<<dim3(4, H * NB), 256, SMEM_FA>>>(
                qh, ql, kh, kl, vh, vl, attn, ch, cl,
                self ? tgt_seq : src_seq, self ? 1 : 0, scale);
            // proj -> y (fp32)
            const bf* pwh = ph + ((long long)l * 2 + (self ? 0 : 1)) * DD;
            const bf* pwl = pl + ((long long)l * 2 + (self ? 0 : 1)) * DD;
            const float* pb = (self ? slf_pb : enc_pb) + (long long)l * D;
            { GArgs a = {ch, cl, D, 0, 0, pwh, pwl, D, 0, 0,
                         y, nullptr, nullptr, D, 0, 0, T, D, D, 1, 1, 1.f, pb, 0, 0};
              g128(a); }
            add_ln_kernel<<<T, 256>>>(y, x, xh, xl,
                (self ? slf_g : enc_g) + (long long)l * D,
                (self ? slf_b : enc_b) + (long long)l * D);
        }
        // FFN
        { GArgs a = {xh, xl, D, 0, 0, f1h + (long long)l * DI * D,
                     f1l + (long long)l * DI * D, D, 0, 0,
                     nullptr, hh, hl, DI, 0, 0, T, DI, D, 1, 1, 1.f,
                     ffn_b1 + (long long)l * DI, 1, 1};
          g128(a); }
        { GArgs a = {hh, hl, DI, 0, 0, f2h + (long long)l * D * DI,
                     f2l + (long long)l * D * DI, DI, 0, 0,
                     y, nullptr, nullptr, D, 0, 0, T, D, DI, 1, 1, 1.f,
                     ffn_b2 + (long long)l * D, 0, 0};
          g128(a); }
        add_ln_kernel<<<T, 256>>>(y, x, xh, xl,
            ffn_g + (long long)l * D, ffn_b + (long long)l * D);
    }

    copy_kernel<<<2048, 256>>>(x, out, X_SIZE);
}